// round 12
// baseline (speedup 1.0000x reference)
#include <cuda_runtime.h>
#include <cuda_fp16.h>
#include <stdint.h>
#include <math.h>

#define N_TOK 2048
#define C_DIM 1024
#define NHEAD 8
#define HD    128
#define NGRP  32
#define HW    64
#define PAD   40    // GEMM smem stride (halfs)
#define ATS   136   // attention smem stride (halfs)

// ---------------- scratch ----------------------------------------------------
__device__ float g_feat[N_TOK * C_DIM];
__device__ float g_coef[N_TOK * C_DIM];
__device__ int   g_bidx[N_TOK];
__device__ int   g_cnt [NGRP];
__device__ int   g_list[NGRP * N_TOK];
__device__ __half g_f   [N_TOK * C_DIM];
__device__ __half g_qkvh[N_TOK * 3 * C_DIM];
__device__ __half g_wq  [3 * C_DIM * C_DIM];
__device__ __half g_wo  [C_DIM * C_DIM];
__device__ __half g_a   [N_TOK * C_DIM];

__device__ __forceinline__ uint32_t smem_u32(const void* p) {
    uint32_t a;
    asm("{ .reg .u64 t; cvta.to.shared.u64 t, %1; cvt.u32.u64 %0, t; }" : "=r"(a) : "l"(p));
    return a;
}
__device__ __forceinline__ void cp16(uint32_t dst, const void* src) {
    asm volatile("cp.async.cg.shared.global [%0], [%1], 16;" :: "r"(dst), "l"(src));
}
#define MMA16816(d, a, b)                                                       \
    asm volatile("mma.sync.aligned.m16n8k16.row.col.f32.f16.f16.f32 "           \
        "{%0,%1,%2,%3}, {%4,%5,%6,%7}, {%8,%9}, {%0,%1,%2,%3};"                 \
        : "+f"((d)[0]), "+f"((d)[1]), "+f"((d)[2]), "+f"((d)[3])                \
        : "r"((a)[0]), "r"((a)[1]), "r"((a)[2]), "r"((a)[3]),                   \
          "r"((b)[0]), "r"((b)[1]))
#define LDSM4(r, addr)                                                          \
    asm volatile("ldmatrix.sync.aligned.m8n8.x4.shared.b16 {%0,%1,%2,%3}, [%4];"\
        : "=r"((r)[0]), "=r"((r)[1]), "=r"((r)[2]), "=r"((r)[3]) : "r"(addr))
#define LDSM4T(r, addr)                                                         \
    asm volatile("ldmatrix.sync.aligned.m8n8.x4.trans.shared.b16 {%0,%1,%2,%3}, [%4];"\
        : "=r"((r)[0]), "=r"((r)[1]), "=r"((r)[2]), "=r"((r)[3]) : "r"(addr))

// ---------------- 1) groups --------------------------------------------------
__global__ void k_groups(const int* __restrict__ raw) {
    __shared__ int sb[N_TOK];
    __shared__ int s64;
    if (threadIdx.x == 0) {
        int acc = 0;
        #pragma unroll
        for (int i = 0; i < 32; i++) acc |= raw[2 * i + 1];
        s64 = (acc == 0);
    }
    __syncthreads();
    for (int i = threadIdx.x; i < N_TOK; i += blockDim.x)
        sb[i] = s64 ? raw[2 * i] : raw[i];
    __syncthreads();
    int i = blockIdx.x * blockDim.x + threadIdx.x;
    if (blockIdx.x == 0) {
        for (int j = threadIdx.x; j < N_TOK; j += blockDim.x) g_bidx[j] = sb[j];
    }
    int b = sb[i];
    int pos = 0;
    for (int j = 0; j < i; j++) pos += (sb[j] == b) ? 1 : 0;
    g_list[b * N_TOK + pos] = i;
    if (blockIdx.x == 0 && threadIdx.x < NGRP) {
        int c = 0;
        for (int j = 0; j < N_TOK; j++) c += (sb[j] == (int)threadIdx.x) ? 1 : 0;
        g_cnt[threadIdx.x] = c;
    }
}

// ---------------- 2) feat = mean over H*W (measured 81% DRAM peak) ----------
__global__ void k_mean(const float* __restrict__ x) {
    const float4* x4 = (const float4*)x;
    int gw    = (blockIdx.x * blockDim.x + threadIdx.x) >> 5;
    int lane  = threadIdx.x & 31;
    int nwarp = (gridDim.x * blockDim.x) >> 5;
    const int CHUNKS = N_TOK * C_DIM / 16;
    for (int ch = gw; ch < CHUNKS; ch += nwarp) {
        size_t base = (size_t)ch * 256 + lane;
        float4 v[8];
        #pragma unroll
        for (int j = 0; j < 8; j++) v[j] = __ldcs(&x4[base + 32 * j]);
        float s[8];
        #pragma unroll
        for (int j = 0; j < 8; j++) s[j] = (v[j].x + v[j].y) + (v[j].z + v[j].w);
        #pragma unroll
        for (int j = 0; j < 8; j++) {
            s[j] += __shfl_xor_sync(0xffffffffu, s[j], 8);
            s[j] += __shfl_xor_sync(0xffffffffu, s[j], 4);
            s[j] += __shfl_xor_sync(0xffffffffu, s[j], 2);
            s[j] += __shfl_xor_sync(0xffffffffu, s[j], 1);
        }
        if (lane == 0 || lane == 16) {
            int r0 = ch * 16 + (lane >> 4);
            #pragma unroll
            for (int j = 0; j < 8; j++) g_feat[r0 + 2 * j] = s[j] * (1.0f / 64.0f);
        }
    }
}

// ---------------- 3) LayerNorm, emit fp16 ------------------------------------
__global__ void k_ln(const float* __restrict__ w, const float* __restrict__ b) {
    int row = blockIdx.x, tid = threadIdx.x;
    int lane = tid & 31, warp = tid >> 5;
    float4 v = ((const float4*)g_feat)[row * 256 + tid];
    float s  = v.x + v.y + v.z + v.w;
    float sq = v.x * v.x + v.y * v.y + v.z * v.z + v.w * v.w;
    #pragma unroll
    for (int off = 16; off; off >>= 1) {
        s  += __shfl_xor_sync(0xffffffffu, s,  off);
        sq += __shfl_xor_sync(0xffffffffu, sq, off);
    }
    __shared__ float rs[8], rq[8];
    if (lane == 0) { rs[warp] = s; rq[warp] = sq; }
    __syncthreads();
    float S = 0.f, SQ = 0.f;
    #pragma unroll
    for (int i = 0; i < 8; i++) { S += rs[i]; SQ += rq[i]; }
    float mu   = S * (1.0f / C_DIM);
    float var  = SQ * (1.0f / C_DIM) - mu * mu;
    float rstd = rsqrtf(var + 1e-5f);
    float4 wv = ((const float4*)w)[tid], bv = ((const float4*)b)[tid];
    __half hs[4];
    hs[0] = __float2half_rn((v.x - mu) * rstd * wv.x + bv.x);
    hs[1] = __float2half_rn((v.y - mu) * rstd * wv.y + bv.y);
    hs[2] = __float2half_rn((v.z - mu) * rstd * wv.z + bv.z);
    hs[3] = __float2half_rn((v.w - mu) * rstd * wv.w + bv.w);
    *(uint2*)&g_f[row * C_DIM + tid * 4] = *(uint2*)hs;
}

// ---------------- 3b) fp32 -> fp16 (weights) ---------------------------------
__global__ void k_half(const float* __restrict__ src, __half* __restrict__ dst, int n4) {
    int i = blockIdx.x * blockDim.x + threadIdx.x;
    if (i >= n4) return;
    float4 v = __ldcs(&((const float4*)src)[i]);
    __half hs[4] = { __float2half_rn(v.x), __float2half_rn(v.y),
                     __float2half_rn(v.z), __float2half_rn(v.w) };
    *(uint2*)&dst[i * 4] = *(uint2*)hs;
}

// ---------------- 4) HMMA GEMM, 64x128 tile, cp.async 2-stage ----------------
// C[M,N] = A[M,K] B[N,K]^T + bias. 8 warps as 2(M)x4(N), warp tile 32x32.
// mode 0: write fp16 to Ch. mode 1: write fp32 coef = valid?gamma*(acc+b):0.
__global__ void __launch_bounds__(256)
k_hgemm(const __half* __restrict__ A, const __half* __restrict__ B,
        const float* __restrict__ bias, float* __restrict__ Cf, __half* __restrict__ Ch,
        int Ncols, int mode, const float* __restrict__ gamma) {
    __shared__ __align__(16) __half sA[2][64 * PAD];
    __shared__ __align__(16) __half sB[2][128 * PAD];

    const int tid = threadIdx.x, warp = tid >> 5, lane = tid & 31;
    const int wm = warp >> 2, wn = warp & 3;       // 2 x 4 warp grid
    const int bM = blockIdx.y * 64, bN = blockIdx.x * 128;

    float acc[2][4][4];
    #pragma unroll
    for (int i = 0; i < 2; i++)
        #pragma unroll
        for (int j = 0; j < 4; j++)
            #pragma unroll
            for (int c = 0; c < 4; c++) acc[i][j][c] = 0.f;

    const int lr = tid >> 2, lc = (tid & 3) * 8;   // 64 rows x 4 slots
    const int a_row = lane & 15, a_k = (lane >> 4) * 8;
    const int b_row = (lane & 7) + ((lane >> 4) << 3);
    const int b_k   = ((lane >> 3) & 1) * 8;
    const uint32_t sA_b = smem_u32(sA), sB_b = smem_u32(sB);

    #define LOAD_STAGE(kc, st) do {                                           \
        uint32_t soA = (uint32_t)(st) * (64 * PAD * 2);                       \
        uint32_t soB = (uint32_t)(st) * (128 * PAD * 2);                      \
        size_t ga0 = (size_t)(bM + lr)      * C_DIM + (kc) * 32 + lc;         \
        size_t gb0 = (size_t)(bN + lr)      * C_DIM + (kc) * 32 + lc;         \
        size_t gb1 = (size_t)(bN + lr + 64) * C_DIM + (kc) * 32 + lc;         \
        cp16(sA_b + soA + (lr * PAD + lc) * 2,        A + ga0);               \
        cp16(sB_b + soB + (lr * PAD + lc) * 2,        B + gb0);               \
        cp16(sB_b + soB + ((lr + 64) * PAD + lc) * 2, B + gb1);               \
        asm volatile("cp.async.commit_group;");                               \
    } while (0)

    LOAD_STAGE(0, 0);
    for (int kc = 0; kc < 32; kc++) {
        int cur = kc & 1;
        if (kc < 31) {
            LOAD_STAGE(kc + 1, cur ^ 1);
            asm volatile("cp.async.wait_group 1;");
        } else {
            asm volatile("cp.async.wait_group 0;");
        }
        __syncthreads();
        uint32_t soA = (uint32_t)cur * (64 * PAD * 2);
        uint32_t soB = (uint32_t)cur * (128 * PAD * 2);
        #pragma unroll
        for (int ks = 0; ks < 32; ks += 16) {
            uint32_t aF[2][4], bF[4][2];
            #pragma unroll
            for (int i = 0; i < 2; i++) {
                uint32_t off = soA + (uint32_t)((wm * 32 + i * 16 + a_row) * PAD + ks + a_k) * 2;
                LDSM4(aF[i], sA_b + off);
            }
            #pragma unroll
            for (int jj = 0; jj < 2; jj++) {
                uint32_t off = soB + (uint32_t)((wn * 32 + jj * 16 + b_row) * PAD + ks + b_k) * 2;
                uint32_t r[4];
                LDSM4(r, sB_b + off);
                bF[jj * 2 + 0][0] = r[0]; bF[jj * 2 + 0][1] = r[1];
                bF[jj * 2 + 1][0] = r[2]; bF[jj * 2 + 1][1] = r[3];
            }
            #pragma unroll
            for (int i = 0; i < 2; i++)
                #pragma unroll
                for (int j = 0; j < 4; j++)
                    MMA16816(acc[i][j], aF[i], bF[j]);
        }
        __syncthreads();
    }

    const int g4 = lane >> 2, t4 = lane & 3;
    #pragma unroll
    for (int i = 0; i < 2; i++) {
        int r0 = bM + wm * 32 + i * 16 + g4;
        int r1 = r0 + 8;
        float gm0 = 1.f, gm1 = 1.f;
        if (mode == 1) {
            gm0 = (g_cnt[g_bidx[r0]] > 1) ? gamma[0] : 0.0f;
            gm1 = (g_cnt[g_bidx[r1]] > 1) ? gamma[0] : 0.0f;
        }
        #pragma unroll
        for (int j = 0; j < 4; j++) {
            int c = bN + wn * 32 + j * 8 + 2 * t4;
            float b0 = bias[c], b1 = bias[c + 1];
            if (mode == 1) {
                float2 o0 = { (acc[i][j][0] + b0) * gm0, (acc[i][j][1] + b1) * gm0 };
                float2 o1 = { (acc[i][j][2] + b0) * gm1, (acc[i][j][3] + b1) * gm1 };
                *(float2*)&Cf[(size_t)r0 * Ncols + c] = o0;
                *(float2*)&Cf[(size_t)r1 * Ncols + c] = o1;
            } else {
                __half h0[2] = { __float2half_rn(acc[i][j][0] + b0),
                                 __float2half_rn(acc[i][j][1] + b1) };
                __half h1[2] = { __float2half_rn(acc[i][j][2] + b0),
                                 __float2half_rn(acc[i][j][3] + b1) };
                *(uint32_t*)&Ch[(size_t)r0 * Ncols + c] = *(uint32_t*)h0;
                *(uint32_t*)&Ch[(size_t)r1 * Ncols + c] = *(uint32_t*)h1;
            }
        }
    }
}

// ---------------- 5) flash attention with HMMA (R10-proven) ------------------
#define QCH 32
__global__ void __launch_bounds__(128) k_attn() {
    int bx = blockIdx.x;
    int qc = bx & (QCH - 1);
    int g  = (bx >> 5) & (NGRP - 1);
    int h  = bx >> 10;
    int m  = g_cnt[g];
    int q0 = qc * 64;
    if (q0 >= m) return;

    int tid = threadIdx.x, w = tid >> 5, lane = tid & 31;
    __shared__ __align__(16) __half Qs[64 * ATS];
    __shared__ __align__(16) __half Ks[32 * ATS];
    __shared__ __align__(16) __half Vs[32 * ATS];
    const uint32_t qs_b = smem_u32(Qs), ks_b = smem_u32(Ks), vs_b = smem_u32(Vs);

    #pragma unroll
    for (int it = 0; it < 8; it++) {
        int p = tid + it * 128;
        int r = p >> 4, c = p & 15;
        int qi = q0 + r;
        uint4 v = {0, 0, 0, 0};
        if (qi < m) {
            int tok = g_list[g * N_TOK + qi];
            v = *(const uint4*)&g_qkvh[(size_t)tok * 3072 + h * HD + c * 8];
        }
        *(uint4*)&Qs[r * ATS + c * 8] = v;
    }
    __syncthreads();

    const int a_row = lane & 15, a_k = (lane >> 4) * 8;
    uint32_t qf[8][4];
    #pragma unroll
    for (int ks = 0; ks < 8; ks++) {
        uint32_t off = (uint32_t)((w * 16 + a_row) * ATS + ks * 16 + a_k) * 2;
        LDSM4(qf[ks], qs_b + off);
    }

    float o[16][4];
    #pragma unroll
    for (int n = 0; n < 16; n++) { o[n][0] = o[n][1] = o[n][2] = o[n][3] = 0.f; }
    float mx0 = -1e30f, mx1 = -1e30f, l0 = 0.f, l1 = 0.f;

    const int b_row = (lane & 7) + ((lane >> 4) << 3);
    const int b_k   = ((lane >> 3) & 1) * 8;
    const int vrow  = (lane & 7) + ((lane >> 3) & 1) * 8;
    const int vcol  = (lane >> 4) * 8;
    const float SC  = 0.08838834764831845f;

    for (int kbase = 0; kbase < m; kbase += 32) {
        __syncthreads();
        #pragma unroll
        for (int it = 0; it < 8; it++) {
            int p = tid + it * 128;
            int isV = p >> 9;
            int q = p & 511;
            int r = q >> 4, c = q & 15;
            int kj = kbase + r;
            uint4 v = {0, 0, 0, 0};
            if (kj < m) {
                int tok = g_list[g * N_TOK + kj];
                v = *(const uint4*)&g_qkvh[(size_t)tok * 3072 + (1 + isV) * C_DIM + h * HD + c * 8];
            }
            if (isV) *(uint4*)&Vs[r * ATS + c * 8] = v;
            else     *(uint4*)&Ks[r * ATS + c * 8] = v;
        }
        __syncthreads();

        float s[4][4];
        #pragma unroll
        for (int T = 0; T < 4; T++) { s[T][0] = s[T][1] = s[T][2] = s[T][3] = 0.f; }
        #pragma unroll
        for (int ks = 0; ks < 8; ks++) {
            uint32_t r0[4], r1[4];
            LDSM4(r0, ks_b + (uint32_t)((0  + b_row) * ATS + ks * 16 + b_k) * 2);
            LDSM4(r1, ks_b + (uint32_t)((16 + b_row) * ATS + ks * 16 + b_k) * 2);
            uint32_t bA[2] = { r0[0], r0[1] }, bB[2] = { r0[2], r0[3] };
            uint32_t bC[2] = { r1[0], r1[1] }, bD[2] = { r1[2], r1[3] };
            MMA16816(s[0], qf[ks], bA);
            MMA16816(s[1], qf[ks], bB);
            MMA16816(s[2], qf[ks], bC);
            MMA16816(s[3], qf[ks], bD);
        }

        int cbase = kbase + 2 * (lane & 3);
        #pragma unroll
        for (int T = 0; T < 4; T++) {
            int k0 = cbase + T * 8;
            s[T][0] = (k0     < m) ? s[T][0] * SC : -1e30f;
            s[T][1] = (k0 + 1 < m) ? s[T][1] * SC : -1e30f;
            s[T][2] = (k0     < m) ? s[T][2] * SC : -1e30f;
            s[T][3] = (k0 + 1 < m) ? s[T][3] * SC : -1e30f;
        }

        float m0 = s[0][0], m1 = s[0][2];
        #pragma unroll
        for (int T = 0; T < 4; T++) {
            m0 = fmaxf(m0, fmaxf(s[T][0], s[T][1]));
            m1 = fmaxf(m1, fmaxf(s[T][2], s[T][3]));
        }
        m0 = fmaxf(m0, __shfl_xor_sync(0xffffffffu, m0, 1));
        m0 = fmaxf(m0, __shfl_xor_sync(0xffffffffu, m0, 2));
        m1 = fmaxf(m1, __shfl_xor_sync(0xffffffffu, m1, 1));
        m1 = fmaxf(m1, __shfl_xor_sync(0xffffffffu, m1, 2));
        float mn0 = fmaxf(mx0, m0), mn1 = fmaxf(mx1, m1);
        float c0 = __expf(mx0 - mn0), c1 = __expf(mx1 - mn1);

        float p[4][4];
        float s0 = 0.f, s1 = 0.f;
        #pragma unroll
        for (int T = 0; T < 4; T++) {
            p[T][0] = __expf(s[T][0] - mn0);
            p[T][1] = __expf(s[T][1] - mn0);
            p[T][2] = __expf(s[T][2] - mn1);
            p[T][3] = __expf(s[T][3] - mn1);
            s0 += p[T][0] + p[T][1];
            s1 += p[T][2] + p[T][3];
        }
        s0 += __shfl_xor_sync(0xffffffffu, s0, 1);
        s0 += __shfl_xor_sync(0xffffffffu, s0, 2);
        s1 += __shfl_xor_sync(0xffffffffu, s1, 1);
        s1 += __shfl_xor_sync(0xffffffffu, s1, 2);
        l0 = l0 * c0 + s0;
        l1 = l1 * c1 + s1;
        mx0 = mn0; mx1 = mn1;

        #pragma unroll
        for (int n = 0; n < 16; n++) {
            o[n][0] *= c0; o[n][1] *= c0; o[n][2] *= c1; o[n][3] *= c1;
        }

        uint32_t pf[2][4];
        #pragma unroll
        for (int kst = 0; kst < 2; kst++) {
            int T0 = kst * 2;
            __half2 h0 = __floats2half2_rn(p[T0][0],     p[T0][1]);
            __half2 h1 = __floats2half2_rn(p[T0][2],     p[T0][3]);
            __half2 h2 = __floats2half2_rn(p[T0 + 1][0], p[T0 + 1][1]);
            __half2 h3 = __floats2half2_rn(p[T0 + 1][2], p[T0 + 1][3]);
            pf[kst][0] = *(uint32_t*)&h0;
            pf[kst][1] = *(uint32_t*)&h1;
            pf[kst][2] = *(uint32_t*)&h2;
            pf[kst][3] = *(uint32_t*)&h3;
        }

        #pragma unroll
        for (int kst = 0; kst < 2; kst++) {
            #pragma unroll
            for (int dt = 0; dt < 8; dt++) {
                uint32_t r[4];
                LDSM4T(r, vs_b + (uint32_t)((kst * 16 + vrow) * ATS + dt * 16 + vcol) * 2);
                uint32_t bA[2] = { r[0], r[1] }, bB[2] = { r[2], r[3] };
                MMA16816(o[dt * 2],     pf[kst], bA);
                MMA16816(o[dt * 2 + 1], pf[kst], bB);
            }
        }
    }

    float inv0 = 1.0f / l0, inv1 = 1.0f / l1;
    int qi0 = q0 + w * 16 + (lane >> 2);
    int qi1 = qi0 + 8;
    int tok0 = (qi0 < m) ? g_list[g * N_TOK + qi0] : -1;
    int tok1 = (qi1 < m) ? g_list[g * N_TOK + qi1] : -1;
    int colb = h * HD + 2 * (lane & 3);
    #pragma unroll
    for (int dt = 0; dt < 16; dt++) {
        if (tok0 >= 0) {
            __half2 hv = __floats2half2_rn(o[dt][0] * inv0, o[dt][1] * inv0);
            *(uint32_t*)&g_a[(size_t)tok0 * C_DIM + colb + dt * 8] = *(uint32_t*)&hv;
        }
        if (tok1 >= 0) {
            __half2 hv = __floats2half2_rn(o[dt][2] * inv1, o[dt][3] * inv1);
            *(uint32_t*)&g_a[(size_t)tok1 * C_DIM + colb + dt * 8] = *(uint32_t*)&hv;
        }
    }
}

// ---------------- 6) y = x + coef[n,c] ---------------------------------------
__global__ void k_add(const float* __restrict__ x, float* __restrict__ y) {
    const float4* x4 = (const float4*)x;
    float4* y4 = (float4*)y;
    const int total = N_TOK * C_DIM * (HW / 4);
    int stride = gridDim.x * blockDim.x;
    for (int i = blockIdx.x * blockDim.x + threadIdx.x; i < total; i += stride) {
        float c = g_coef[i >> 4];
        float4 v = x4[i];
        v.x += c; v.y += c; v.z += c; v.w += c;
        y4[i] = v;
    }
}

// ---------------- launch ------------------------------------------------------
extern "C" void kernel_launch(void* const* d_in, const int* in_sizes, int n_in,
                              void* d_out, int out_size) {
    const float* x          = (const float*)d_in[0];
    const int*   braw       = (const int*)  d_in[1];
    const float* ln_w       = (const float*)d_in[2];
    const float* ln_b       = (const float*)d_in[3];
    const float* in_proj_w  = (const float*)d_in[4];
    const float* in_proj_b  = (const float*)d_in[5];
    const float* out_proj_w = (const float*)d_in[6];
    const float* out_proj_b = (const float*)d_in[7];
    const float* gamma      = (const float*)d_in[8];
    float* y = (float*)d_out;

    __half *p_f, *p_wq, *p_wo, *p_a, *p_qkvh;
    float *p_coef;
    cudaGetSymbolAddress((void**)&p_f,    g_f);
    cudaGetSymbolAddress((void**)&p_wq,   g_wq);
    cudaGetSymbolAddress((void**)&p_wo,   g_wo);
    cudaGetSymbolAddress((void**)&p_a,    g_a);
    cudaGetSymbolAddress((void**)&p_qkvh, g_qkvh);
    cudaGetSymbolAddress((void**)&p_coef, g_coef);

    // slot 4 (ncu) = QKV GEMM
    k_half   <<<3072, 256>>>(in_proj_w,  p_wq, 3 * C_DIM * C_DIM / 4);
    k_mean   <<<1184, 256>>>(x);
    k_ln     <<<N_TOK, 256>>>(ln_w, ln_b);
    k_hgemm  <<<dim3(24, 32), 256>>>(p_f, p_wq, in_proj_b, nullptr, p_qkvh,
                                     3 * C_DIM, 0, nullptr);
    k_groups <<<8, 256>>>(braw);
    k_half   <<<1024, 256>>>(out_proj_w, p_wo, C_DIM * C_DIM / 4);
    k_attn   <<<NHEAD * NGRP * QCH, 128>>>();
    k_hgemm  <<<dim3(8, 32), 256>>>(p_a, p_wo, out_proj_b, p_coef, nullptr,
                                    C_DIM, 1, gamma);
    k_add    <<<32768, 256>>>(x, y);
}

// round 15
// speedup vs baseline: 1.0586x; 1.0586x over previous
#include <cuda_runtime.h>
#include <cuda_fp16.h>
#include <stdint.h>
#include <math.h>

#define N_TOK 2048
#define C_DIM 1024
#define NHEAD 8
#define HD    128
#define NGRP  32
#define HW    64
#define PAD   40    // GEMM smem stride (halfs)
#define ATS   136   // attention smem stride (halfs)
#define WQ4   (3 * C_DIM * C_DIM / 4)   // 786432 float4 items
#define WO4   (C_DIM * C_DIM / 4)       // 262144 float4 items
#define MEANB 1184

// ---------------- scratch ----------------------------------------------------
__device__ float g_feat[N_TOK * C_DIM];
__device__ float g_coef[N_TOK * C_DIM];
__device__ int   g_bidx[N_TOK];
__device__ int   g_cnt [NGRP];
__device__ int   g_list[NGRP * N_TOK];
__device__ __half g_f   [N_TOK * C_DIM];
__device__ __half g_qkvh[N_TOK * 3 * C_DIM];
__device__ __half g_wq  [3 * C_DIM * C_DIM];
__device__ __half g_wo  [C_DIM * C_DIM];
__device__ __half g_a   [N_TOK * C_DIM];

__device__ __forceinline__ uint32_t smem_u32(const void* p) {
    uint32_t a;
    asm("{ .reg .u64 t; cvta.to.shared.u64 t, %1; cvt.u32.u64 %0, t; }" : "=r"(a) : "l"(p));
    return a;
}
__device__ __forceinline__ void cp16(uint32_t dst, const void* src) {
    asm volatile("cp.async.cg.shared.global [%0], [%1], 16;" :: "r"(dst), "l"(src));
}
#define MMA16816(d, a, b)                                                       \
    asm volatile("mma.sync.aligned.m16n8k16.row.col.f32.f16.f16.f32 "           \
        "{%0,%1,%2,%3}, {%4,%5,%6,%7}, {%8,%9}, {%0,%1,%2,%3};"                 \
        : "+f"((d)[0]), "+f"((d)[1]), "+f"((d)[2]), "+f"((d)[3])                \
        : "r"((a)[0]), "r"((a)[1]), "r"((a)[2]), "r"((a)[3]),                   \
          "r"((b)[0]), "r"((b)[1]))
#define LDSM4(r, addr)                                                          \
    asm volatile("ldmatrix.sync.aligned.m8n8.x4.shared.b16 {%0,%1,%2,%3}, [%4];"\
        : "=r"((r)[0]), "=r"((r)[1]), "=r"((r)[2]), "=r"((r)[3]) : "r"(addr))
#define LDSM4T(r, addr)                                                         \
    asm volatile("ldmatrix.sync.aligned.m8n8.x4.trans.shared.b16 {%0,%1,%2,%3}, [%4];"\
        : "=r"((r)[0]), "=r"((r)[1]), "=r"((r)[2]), "=r"((r)[3]) : "r"(addr))

// ---------------- 1) k_pre: mean over H*W + wq fp32->fp16 --------------------
// Blocks [0, MEANB): mean (measured 81% DRAM peak). Blocks [MEANB, MEANB+3072): wq convert.
__global__ void k_pre(const float* __restrict__ x,
                      const float* __restrict__ wq_src, __half* __restrict__ wq_dst) {
    if (blockIdx.x < MEANB) {
        const float4* x4 = (const float4*)x;
        int gw    = (blockIdx.x * blockDim.x + threadIdx.x) >> 5;
        int lane  = threadIdx.x & 31;
        int nwarp = (MEANB * 256) >> 5;
        const int CHUNKS = N_TOK * C_DIM / 16;
        for (int ch = gw; ch < CHUNKS; ch += nwarp) {
            size_t base = (size_t)ch * 256 + lane;
            float4 v[8];
            #pragma unroll
            for (int j = 0; j < 8; j++) v[j] = __ldcs(&x4[base + 32 * j]);
            float s[8];
            #pragma unroll
            for (int j = 0; j < 8; j++) s[j] = (v[j].x + v[j].y) + (v[j].z + v[j].w);
            #pragma unroll
            for (int j = 0; j < 8; j++) {
                s[j] += __shfl_xor_sync(0xffffffffu, s[j], 8);
                s[j] += __shfl_xor_sync(0xffffffffu, s[j], 4);
                s[j] += __shfl_xor_sync(0xffffffffu, s[j], 2);
                s[j] += __shfl_xor_sync(0xffffffffu, s[j], 1);
            }
            if (lane == 0 || lane == 16) {
                int r0 = ch * 16 + (lane >> 4);
                #pragma unroll
                for (int j = 0; j < 8; j++) g_feat[r0 + 2 * j] = s[j] * (1.0f / 64.0f);
            }
        }
    } else {
        int i = (blockIdx.x - MEANB) * blockDim.x + threadIdx.x;
        if (i < WQ4) {
            float4 v = __ldcs(&((const float4*)wq_src)[i]);
            __half hs[4] = { __float2half_rn(v.x), __float2half_rn(v.y),
                             __float2half_rn(v.z), __float2half_rn(v.w) };
            *(uint2*)&wq_dst[i * 4] = *(uint2*)hs;
        }
    }
}

// ---------------- 3) LayerNorm: warp per token --------------------------------
__global__ void __launch_bounds__(256) k_ln(const float* __restrict__ w,
                                            const float* __restrict__ b) {
    int warp = threadIdx.x >> 5, lane = threadIdx.x & 31;
    int tok = blockIdx.x * 8 + warp;
    const float4* f4 = (const float4*)g_feat + (size_t)tok * 256;
    float4 v[8];
    #pragma unroll
    for (int i = 0; i < 8; i++) v[i] = f4[lane + i * 32];
    float s = 0.f, sq = 0.f;
    #pragma unroll
    for (int i = 0; i < 8; i++) {
        s  += (v[i].x + v[i].y) + (v[i].z + v[i].w);
        sq += (v[i].x * v[i].x + v[i].y * v[i].y)
            + (v[i].z * v[i].z + v[i].w * v[i].w);
    }
    #pragma unroll
    for (int off = 16; off; off >>= 1) {
        s  += __shfl_xor_sync(0xffffffffu, s,  off);
        sq += __shfl_xor_sync(0xffffffffu, sq, off);
    }
    float mu   = s * (1.0f / C_DIM);
    float var  = sq * (1.0f / C_DIM) - mu * mu;
    float rstd = rsqrtf(var + 1e-5f);
    #pragma unroll
    for (int i = 0; i < 8; i++) {
        int c4 = lane + i * 32;
        float4 wv = ((const float4*)w)[c4], bv = ((const float4*)b)[c4];
        __half hs[4];
        hs[0] = __float2half_rn((v[i].x - mu) * rstd * wv.x + bv.x);
        hs[1] = __float2half_rn((v[i].y - mu) * rstd * wv.y + bv.y);
        hs[2] = __float2half_rn((v[i].z - mu) * rstd * wv.z + bv.z);
        hs[3] = __float2half_rn((v[i].w - mu) * rstd * wv.w + bv.w);
        *(uint2*)&g_f[(size_t)tok * C_DIM + c4 * 4] = *(uint2*)hs;
    }
}

// ---------------- 4) HMMA GEMM (R10-proven) + fused side-work row -------------
// mode 0: write fp16 to Ch; extra row (blockIdx.y == gridDim.y-1) does
//         groups + wo fp32->fp16 concurrently (gemm is DRAM-idle).
// mode 1: write fp32 coef = valid ? gamma*(acc+bias) : 0.
__global__ void __launch_bounds__(256)
k_hgemm(const __half* __restrict__ A, const __half* __restrict__ B,
        const float* __restrict__ bias, float* __restrict__ Cf, __half* __restrict__ Ch,
        int Ncols, int mode, const float* __restrict__ gamma,
        int extra, const int* __restrict__ braw,
        const float* __restrict__ wo_src, __half* __restrict__ wo_dst) {
    __shared__ __align__(16) __half sA[2][128 * PAD];
    __shared__ __align__(16) __half sB[2][128 * PAD];

    const int tid = threadIdx.x;

    if (extra && blockIdx.y == gridDim.y - 1) {
        int bx = blockIdx.x;
        if (bx < 8) {
            // ---- groups (reuses sA as scan buffer) ----
            int* sb = (int*)sA;                    // 2048 ints = 8KB << 40KB
            __shared__ int s64;
            if (tid == 0) {
                int acc = 0;
                #pragma unroll
                for (int i = 0; i < 32; i++) acc |= braw[2 * i + 1];
                s64 = (acc == 0);
            }
            __syncthreads();
            for (int i = tid; i < N_TOK; i += 256)
                sb[i] = s64 ? braw[2 * i] : braw[i];
            __syncthreads();
            int i = bx * 256 + tid;
            if (bx == 0) {
                for (int j = tid; j < N_TOK; j += 256) g_bidx[j] = sb[j];
            }
            int b = sb[i];
            int pos = 0;
            for (int j = 0; j < i; j++) pos += (sb[j] == b) ? 1 : 0;
            g_list[b * N_TOK + pos] = i;
            if (bx == 0 && tid < NGRP) {
                int c = 0;
                for (int j = 0; j < N_TOK; j++) c += (sb[j] == tid) ? 1 : 0;
                g_cnt[tid] = c;
            }
        } else {
            // ---- wo conversion: 16 blocks x 256 threads, stride loop ----
            for (int i = (bx - 8) * 256 + tid; i < WO4; i += 16 * 256) {
                float4 v = __ldcs(&((const float4*)wo_src)[i]);
                __half hs[4] = { __float2half_rn(v.x), __float2half_rn(v.y),
                                 __float2half_rn(v.z), __float2half_rn(v.w) };
                *(uint2*)&wo_dst[i * 4] = *(uint2*)hs;
            }
        }
        return;
    }

    const int warp = tid >> 5, lane = tid & 31;
    const int wm = warp >> 2, wn = warp & 3;
    const int bM = blockIdx.y * 128, bN = blockIdx.x * 128;

    float acc[4][4][4];
    #pragma unroll
    for (int i = 0; i < 4; i++)
        #pragma unroll
        for (int j = 0; j < 4; j++)
            #pragma unroll
            for (int c = 0; c < 4; c++) acc[i][j][c] = 0.f;

    const int lr = tid >> 2, lc = (tid & 3) * 8;
    const int a_row = lane & 15, a_k = (lane >> 4) * 8;
    const int b_row = (lane & 7) + ((lane >> 4) << 3);
    const int b_k   = ((lane >> 3) & 1) * 8;
    const uint32_t sA_b = smem_u32(sA), sB_b = smem_u32(sB);

    #define LOAD_STAGE(kc, st) do {                                           \
        uint32_t so = (uint32_t)(st) * (128 * PAD * 2);                       \
        size_t ga0 = (size_t)(bM + lr)      * C_DIM + (kc) * 32 + lc;         \
        size_t ga1 = (size_t)(bM + lr + 64) * C_DIM + (kc) * 32 + lc;         \
        size_t gb0 = (size_t)(bN + lr)      * C_DIM + (kc) * 32 + lc;         \
        size_t gb1 = (size_t)(bN + lr + 64) * C_DIM + (kc) * 32 + lc;         \
        cp16(sA_b + so + (lr * PAD + lc) * 2,        A + ga0);                \
        cp16(sA_b + so + ((lr + 64) * PAD + lc) * 2, A + ga1);                \
        cp16(sB_b + so + (lr * PAD + lc) * 2,        B + gb0);                \
        cp16(sB_b + so + ((lr + 64) * PAD + lc) * 2, B + gb1);                \
        asm volatile("cp.async.commit_group;");                               \
    } while (0)

    LOAD_STAGE(0, 0);
    for (int kc = 0; kc < 32; kc++) {
        int cur = kc & 1;
        if (kc < 31) {
            LOAD_STAGE(kc + 1, cur ^ 1);
            asm volatile("cp.async.wait_group 1;");
        } else {
            asm volatile("cp.async.wait_group 0;");
        }
        __syncthreads();
        uint32_t so = (uint32_t)cur * (128 * PAD * 2);
        #pragma unroll
        for (int ks = 0; ks < 32; ks += 16) {
            uint32_t aF[4][4], bF[4][2];
            #pragma unroll
            for (int i = 0; i < 4; i++) {
                uint32_t off = so + (uint32_t)((wm * 64 + i * 16 + a_row) * PAD + ks + a_k) * 2;
                LDSM4(aF[i], sA_b + off);
            }
            #pragma unroll
            for (int jj = 0; jj < 2; jj++) {
                uint32_t off = so + (uint32_t)((wn * 32 + jj * 16 + b_row) * PAD + ks + b_k) * 2;
                uint32_t r[4];
                LDSM4(r, sB_b + off);
                bF[jj * 2 + 0][0] = r[0]; bF[jj * 2 + 0][1] = r[1];
                bF[jj * 2 + 1][0] = r[2]; bF[jj * 2 + 1][1] = r[3];
            }
            #pragma unroll
            for (int i = 0; i < 4; i++)
                #pragma unroll
                for (int j = 0; j < 4; j++)
                    MMA16816(acc[i][j], aF[i], bF[j]);
        }
        __syncthreads();
    }

    const int g4 = lane >> 2, t4 = lane & 3;
    #pragma unroll
    for (int i = 0; i < 4; i++) {
        int r0 = bM + wm * 64 + i * 16 + g4;
        int r1 = r0 + 8;
        float gm0 = 1.f, gm1 = 1.f;
        if (mode == 1) {
            gm0 = (g_cnt[g_bidx[r0]] > 1) ? gamma[0] : 0.0f;
            gm1 = (g_cnt[g_bidx[r1]] > 1) ? gamma[0] : 0.0f;
        }
        #pragma unroll
        for (int j = 0; j < 4; j++) {
            int c = bN + wn * 32 + j * 8 + 2 * t4;
            float b0 = bias[c], b1 = bias[c + 1];
            if (mode == 1) {
                float2 o0 = { (acc[i][j][0] + b0) * gm0, (acc[i][j][1] + b1) * gm0 };
                float2 o1 = { (acc[i][j][2] + b0) * gm1, (acc[i][j][3] + b1) * gm1 };
                *(float2*)&Cf[(size_t)r0 * Ncols + c] = o0;
                *(float2*)&Cf[(size_t)r1 * Ncols + c] = o1;
            } else {
                __half h0[2] = { __float2half_rn(acc[i][j][0] + b0),
                                 __float2half_rn(acc[i][j][1] + b1) };
                __half h1[2] = { __float2half_rn(acc[i][j][2] + b0),
                                 __float2half_rn(acc[i][j][3] + b1) };
                *(uint32_t*)&Ch[(size_t)r0 * Ncols + c] = *(uint32_t*)h0;
                *(uint32_t*)&Ch[(size_t)r1 * Ncols + c] = *(uint32_t*)h1;
            }
        }
    }
}

// ---------------- 5) flash attention with HMMA (R10-proven) ------------------
#define QCH 32
__global__ void __launch_bounds__(128) k_attn() {
    int bx = blockIdx.x;
    int qc = bx & (QCH - 1);
    int g  = (bx >> 5) & (NGRP - 1);
    int h  = bx >> 10;
    int m  = g_cnt[g];
    int q0 = qc * 64;
    if (q0 >= m) return;

    int tid = threadIdx.x, w = tid >> 5, lane = tid & 31;
    __shared__ __align__(16) __half Qs[64 * ATS];
    __shared__ __align__(16) __half Ks[32 * ATS];
    __shared__ __align__(16) __half Vs[32 * ATS];
    const uint32_t qs_b = smem_u32(Qs), ks_b = smem_u32(Ks), vs_b = smem_u32(Vs);

    #pragma unroll
    for (int it = 0; it < 8; it++) {
        int p = tid + it * 128;
        int r = p >> 4, c = p & 15;
        int qi = q0 + r;
        uint4 v = {0, 0, 0, 0};
        if (qi < m) {
            int tok = g_list[g * N_TOK + qi];
            v = *(const uint4*)&g_qkvh[(size_t)tok * 3072 + h * HD + c * 8];
        }
        *(uint4*)&Qs[r * ATS + c * 8] = v;
    }
    __syncthreads();

    const int a_row = lane & 15, a_k = (lane >> 4) * 8;
    uint32_t qf[8][4];
    #pragma unroll
    for (int ks = 0; ks < 8; ks++) {
        uint32_t off = (uint32_t)((w * 16 + a_row) * ATS + ks * 16 + a_k) * 2;
        LDSM4(qf[ks], qs_b + off);
    }

    float o[16][4];
    #pragma unroll
    for (int n = 0; n < 16; n++) { o[n][0] = o[n][1] = o[n][2] = o[n][3] = 0.f; }
    float mx0 = -1e30f, mx1 = -1e30f, l0 = 0.f, l1 = 0.f;

    const int b_row = (lane & 7) + ((lane >> 4) << 3);
    const int b_k   = ((lane >> 3) & 1) * 8;
    const int vrow  = (lane & 7) + ((lane >> 3) & 1) * 8;
    const int vcol  = (lane >> 4) * 8;
    const float SC  = 0.08838834764831845f;

    for (int kbase = 0; kbase < m; kbase += 32) {
        __syncthreads();
        #pragma unroll
        for (int it = 0; it < 8; it++) {
            int p = tid + it * 128;
            int isV = p >> 9;
            int q = p & 511;
            int r = q >> 4, c = q & 15;
            int kj = kbase + r;
            uint4 v = {0, 0, 0, 0};
            if (kj < m) {
                int tok = g_list[g * N_TOK + kj];
                v = *(const uint4*)&g_qkvh[(size_t)tok * 3072 + (1 + isV) * C_DIM + h * HD + c * 8];
            }
            if (isV) *(uint4*)&Vs[r * ATS + c * 8] = v;
            else     *(uint4*)&Ks[r * ATS + c * 8] = v;
        }
        __syncthreads();

        float s[4][4];
        #pragma unroll
        for (int T = 0; T < 4; T++) { s[T][0] = s[T][1] = s[T][2] = s[T][3] = 0.f; }
        #pragma unroll
        for (int ks = 0; ks < 8; ks++) {
            uint32_t r0[4], r1[4];
            LDSM4(r0, ks_b + (uint32_t)((0  + b_row) * ATS + ks * 16 + b_k) * 2);
            LDSM4(r1, ks_b + (uint32_t)((16 + b_row) * ATS + ks * 16 + b_k) * 2);
            uint32_t bA[2] = { r0[0], r0[1] }, bB[2] = { r0[2], r0[3] };
            uint32_t bC[2] = { r1[0], r1[1] }, bD[2] = { r1[2], r1[3] };
            MMA16816(s[0], qf[ks], bA);
            MMA16816(s[1], qf[ks], bB);
            MMA16816(s[2], qf[ks], bC);
            MMA16816(s[3], qf[ks], bD);
        }

        int cbase = kbase + 2 * (lane & 3);
        #pragma unroll
        for (int T = 0; T < 4; T++) {
            int k0 = cbase + T * 8;
            s[T][0] = (k0     < m) ? s[T][0] * SC : -1e30f;
            s[T][1] = (k0 + 1 < m) ? s[T][1] * SC : -1e30f;
            s[T][2] = (k0     < m) ? s[T][2] * SC : -1e30f;
            s[T][3] = (k0 + 1 < m) ? s[T][3] * SC : -1e30f;
        }

        float m0 = s[0][0], m1 = s[0][2];
        #pragma unroll
        for (int T = 0; T < 4; T++) {
            m0 = fmaxf(m0, fmaxf(s[T][0], s[T][1]));
            m1 = fmaxf(m1, fmaxf(s[T][2], s[T][3]));
        }
        m0 = fmaxf(m0, __shfl_xor_sync(0xffffffffu, m0, 1));
        m0 = fmaxf(m0, __shfl_xor_sync(0xffffffffu, m0, 2));
        m1 = fmaxf(m1, __shfl_xor_sync(0xffffffffu, m1, 1));
        m1 = fmaxf(m1, __shfl_xor_sync(0xffffffffu, m1, 2));
        float mn0 = fmaxf(mx0, m0), mn1 = fmaxf(mx1, m1);
        float c0 = __expf(mx0 - mn0), c1 = __expf(mx1 - mn1);

        float p[4][4];
        float s0 = 0.f, s1 = 0.f;
        #pragma unroll
        for (int T = 0; T < 4; T++) {
            p[T][0] = __expf(s[T][0] - mn0);
            p[T][1] = __expf(s[T][1] - mn0);
            p[T][2] = __expf(s[T][2] - mn1);
            p[T][3] = __expf(s[T][3] - mn1);
            s0 += p[T][0] + p[T][1];
            s1 += p[T][2] + p[T][3];
        }
        s0 += __shfl_xor_sync(0xffffffffu, s0, 1);
        s0 += __shfl_xor_sync(0xffffffffu, s0, 2);
        s1 += __shfl_xor_sync(0xffffffffu, s1, 1);
        s1 += __shfl_xor_sync(0xffffffffu, s1, 2);
        l0 = l0 * c0 + s0;
        l1 = l1 * c1 + s1;
        mx0 = mn0; mx1 = mn1;

        #pragma unroll
        for (int n = 0; n < 16; n++) {
            o[n][0] *= c0; o[n][1] *= c0; o[n][2] *= c1; o[n][3] *= c1;
        }

        uint32_t pf[2][4];
        #pragma unroll
        for (int kst = 0; kst < 2; kst++) {
            int T0 = kst * 2;
            __half2 h0 = __floats2half2_rn(p[T0][0],     p[T0][1]);
            __half2 h1 = __floats2half2_rn(p[T0][2],     p[T0][3]);
            __half2 h2 = __floats2half2_rn(p[T0 + 1][0], p[T0 + 1][1]);
            __half2 h3 = __floats2half2_rn(p[T0 + 1][2], p[T0 + 1][3]);
            pf[kst][0] = *(uint32_t*)&h0;
            pf[kst][1] = *(uint32_t*)&h1;
            pf[kst][2] = *(uint32_t*)&h2;
            pf[kst][3] = *(uint32_t*)&h3;
        }

        #pragma unroll
        for (int kst = 0; kst < 2; kst++) {
            #pragma unroll
            for (int dt = 0; dt < 8; dt++) {
                uint32_t r[4];
                LDSM4T(r, vs_b + (uint32_t)((kst * 16 + vrow) * ATS + dt * 16 + vcol) * 2);
                uint32_t bA[2] = { r[0], r[1] }, bB[2] = { r[2], r[3] };
                MMA16816(o[dt * 2],     pf[kst], bA);
                MMA16816(o[dt * 2 + 1], pf[kst], bB);
            }
        }
    }

    float inv0 = 1.0f / l0, inv1 = 1.0f / l1;
    int qi0 = q0 + w * 16 + (lane >> 2);
    int qi1 = qi0 + 8;
    int tok0 = (qi0 < m) ? g_list[g * N_TOK + qi0] : -1;
    int tok1 = (qi1 < m) ? g_list[g * N_TOK + qi1] : -1;
    int colb = h * HD + 2 * (lane & 3);
    #pragma unroll
    for (int dt = 0; dt < 16; dt++) {
        if (tok0 >= 0) {
            __half2 hv = __floats2half2_rn(o[dt][0] * inv0, o[dt][1] * inv0);
            *(uint32_t*)&g_a[(size_t)tok0 * C_DIM + colb + dt * 8] = *(uint32_t*)&hv;
        }
        if (tok1 >= 0) {
            __half2 hv = __floats2half2_rn(o[dt][2] * inv1, o[dt][3] * inv1);
            *(uint32_t*)&g_a[(size_t)tok1 * C_DIM + colb + dt * 8] = *(uint32_t*)&hv;
        }
    }
}

// ---------------- 6) y = x + coef[n,c] ---------------------------------------
__global__ void k_add(const float* __restrict__ x, float* __restrict__ y) {
    const float4* x4 = (const float4*)x;
    float4* y4 = (float4*)y;
    const int total = N_TOK * C_DIM * (HW / 4);
    int stride = gridDim.x * blockDim.x;
    for (int i = blockIdx.x * blockDim.x + threadIdx.x; i < total; i += stride) {
        float c = g_coef[i >> 4];
        float4 v = x4[i];
        v.x += c; v.y += c; v.z += c; v.w += c;
        y4[i] = v;
    }
}

// ---------------- launch ------------------------------------------------------
extern "C" void kernel_launch(void* const* d_in, const int* in_sizes, int n_in,
                              void* d_out, int out_size) {
    const float* x          = (const float*)d_in[0];
    const int*   braw       = (const int*)  d_in[1];
    const float* ln_w       = (const float*)d_in[2];
    const float* ln_b       = (const float*)d_in[3];
    const float* in_proj_w  = (const float*)d_in[4];
    const float* in_proj_b  = (const float*)d_in[5];
    const float* out_proj_w = (const float*)d_in[6];
    const float* out_proj_b = (const float*)d_in[7];
    const float* gamma      = (const float*)d_in[8];
    float* y = (float*)d_out;

    __half *p_f, *p_wq, *p_wo, *p_a, *p_qkvh;
    float *p_coef;
    cudaGetSymbolAddress((void**)&p_f,    g_f);
    cudaGetSymbolAddress((void**)&p_wq,   g_wq);
    cudaGetSymbolAddress((void**)&p_wo,   g_wo);
    cudaGetSymbolAddress((void**)&p_a,    g_a);
    cudaGetSymbolAddress((void**)&p_qkvh, g_qkvh);
    cudaGetSymbolAddress((void**)&p_coef, g_coef);

    // Single stream; overlap achieved via block-range fusion.
    // slot 4 (ncu) = k_attn.
    k_pre  <<<MEANB + 3072, 256>>>(x, in_proj_w, p_wq);           // mean + wq convert
    k_ln   <<<256, 256>>>(ln_w, ln_b);
    k_hgemm<<<dim3(24, 17), 256>>>(p_f, p_wq, in_proj_b, nullptr, p_qkvh,
                                   3 * C_DIM, 0, nullptr,
                                   1, braw, out_proj_w, p_wo);    // + groups + wo convert
    k_attn <<<NHEAD * NGRP * QCH, 128>>>();
    k_hgemm<<<dim3(8, 16), 256>>>(p_a, p_wo, out_proj_b, p_coef, nullptr,
                                  C_DIM, 1, gamma,
                                  0, nullptr, nullptr, nullptr);
    k_add  <<<32768, 256>>>(x, y);
}

// round 16
// speedup vs baseline: 1.0804x; 1.0206x over previous
#include <cuda_runtime.h>
#include <cuda_fp16.h>
#include <stdint.h>
#include <math.h>

#define N_TOK 2048
#define C_DIM 1024
#define NHEAD 8
#define HD    128
#define NGRP  32
#define HW    64
#define PAD   40    // GEMM smem stride (halfs)
#define ATS   136   // attention smem stride (halfs)
#define WQ4   (3 * C_DIM * C_DIM / 4)
#define WO4   (C_DIM * C_DIM / 4)
#define MEANB 1184

// ---------------- scratch ----------------------------------------------------
__device__ float g_feat[N_TOK * C_DIM];
__device__ float g_coef[N_TOK * C_DIM];
__device__ int   g_bidx[N_TOK];
__device__ int   g_cnt [NGRP];
__device__ int   g_list[NGRP * N_TOK];
__device__ __half g_f   [N_TOK * C_DIM];
__device__ __half g_qkvh[N_TOK * 3 * C_DIM];
__device__ __half g_wq  [3 * C_DIM * C_DIM];
__device__ __half g_wo  [C_DIM * C_DIM];
__device__ __half g_a   [N_TOK * C_DIM];

__device__ __forceinline__ uint32_t smem_u32(const void* p) {
    uint32_t a;
    asm("{ .reg .u64 t; cvta.to.shared.u64 t, %1; cvt.u32.u64 %0, t; }" : "=r"(a) : "l"(p));
    return a;
}
__device__ __forceinline__ void cp16(uint32_t dst, const void* src) {
    asm volatile("cp.async.cg.shared.global [%0], [%1], 16;" :: "r"(dst), "l"(src));
}
#define MMA16816(d, a, b)                                                       \
    asm volatile("mma.sync.aligned.m16n8k16.row.col.f32.f16.f16.f32 "           \
        "{%0,%1,%2,%3}, {%4,%5,%6,%7}, {%8,%9}, {%0,%1,%2,%3};"                 \
        : "+f"((d)[0]), "+f"((d)[1]), "+f"((d)[2]), "+f"((d)[3])                \
        : "r"((a)[0]), "r"((a)[1]), "r"((a)[2]), "r"((a)[3]),                   \
          "r"((b)[0]), "r"((b)[1]))
#define LDSM4(r, addr)                                                          \
    asm volatile("ldmatrix.sync.aligned.m8n8.x4.shared.b16 {%0,%1,%2,%3}, [%4];"\
        : "=r"((r)[0]), "=r"((r)[1]), "=r"((r)[2]), "=r"((r)[3]) : "r"(addr))
#define LDSM4T(r, addr)                                                         \
    asm volatile("ldmatrix.sync.aligned.m8n8.x4.trans.shared.b16 {%0,%1,%2,%3}, [%4];"\
        : "=r"((r)[0]), "=r"((r)[1]), "=r"((r)[2]), "=r"((r)[3]) : "r"(addr))

// ---------------- 1) k_pre: mean over H*W + wq fp32->fp16 --------------------
__global__ void k_pre(const float* __restrict__ x,
                      const float* __restrict__ wq_src, __half* __restrict__ wq_dst) {
    if (blockIdx.x < MEANB) {
        const float4* x4 = (const float4*)x;
        int gw    = (blockIdx.x * blockDim.x + threadIdx.x) >> 5;
        int lane  = threadIdx.x & 31;
        int nwarp = (MEANB * 256) >> 5;
        const int CHUNKS = N_TOK * C_DIM / 16;
        for (int ch = gw; ch < CHUNKS; ch += nwarp) {
            size_t base = (size_t)ch * 256 + lane;
            float4 v[8];
            #pragma unroll
            for (int j = 0; j < 8; j++) v[j] = __ldcs(&x4[base + 32 * j]);
            float s[8];
            #pragma unroll
            for (int j = 0; j < 8; j++) s[j] = (v[j].x + v[j].y) + (v[j].z + v[j].w);
            #pragma unroll
            for (int j = 0; j < 8; j++) {
                s[j] += __shfl_xor_sync(0xffffffffu, s[j], 8);
                s[j] += __shfl_xor_sync(0xffffffffu, s[j], 4);
                s[j] += __shfl_xor_sync(0xffffffffu, s[j], 2);
                s[j] += __shfl_xor_sync(0xffffffffu, s[j], 1);
            }
            if (lane == 0 || lane == 16) {
                int r0 = ch * 16 + (lane >> 4);
                #pragma unroll
                for (int j = 0; j < 8; j++) g_feat[r0 + 2 * j] = s[j] * (1.0f / 64.0f);
            }
        }
    } else {
        int i = (blockIdx.x - MEANB) * blockDim.x + threadIdx.x;
        if (i < WQ4) {
            float4 v = __ldcs(&((const float4*)wq_src)[i]);
            __half hs[4] = { __float2half_rn(v.x), __float2half_rn(v.y),
                             __float2half_rn(v.z), __float2half_rn(v.w) };
            *(uint2*)&wq_dst[i * 4] = *(uint2*)hs;
        }
    }
}

// ---------------- 3) LayerNorm: warp per token --------------------------------
__global__ void __launch_bounds__(256) k_ln(const float* __restrict__ w,
                                            const float* __restrict__ b) {
    int warp = threadIdx.x >> 5, lane = threadIdx.x & 31;
    int tok = blockIdx.x * 8 + warp;
    const float4* f4 = (const float4*)g_feat + (size_t)tok * 256;
    float4 v[8];
    #pragma unroll
    for (int i = 0; i < 8; i++) v[i] = f4[lane + i * 32];
    float s = 0.f, sq = 0.f;
    #pragma unroll
    for (int i = 0; i < 8; i++) {
        s  += (v[i].x + v[i].y) + (v[i].z + v[i].w);
        sq += (v[i].x * v[i].x + v[i].y * v[i].y)
            + (v[i].z * v[i].z + v[i].w * v[i].w);
    }
    #pragma unroll
    for (int off = 16; off; off >>= 1) {
        s  += __shfl_xor_sync(0xffffffffu, s,  off);
        sq += __shfl_xor_sync(0xffffffffu, sq, off);
    }
    float mu   = s * (1.0f / C_DIM);
    float var  = sq * (1.0f / C_DIM) - mu * mu;
    float rstd = rsqrtf(var + 1e-5f);
    #pragma unroll
    for (int i = 0; i < 8; i++) {
        int c4 = lane + i * 32;
        float4 wv = ((const float4*)w)[c4], bv = ((const float4*)b)[c4];
        __half hs[4];
        hs[0] = __float2half_rn((v[i].x - mu) * rstd * wv.x + bv.x);
        hs[1] = __float2half_rn((v[i].y - mu) * rstd * wv.y + bv.y);
        hs[2] = __float2half_rn((v[i].z - mu) * rstd * wv.z + bv.z);
        hs[3] = __float2half_rn((v[i].w - mu) * rstd * wv.w + bv.w);
        *(uint2*)&g_f[(size_t)tok * C_DIM + c4 * 4] = *(uint2*)hs;
    }
}

// ---------------- 4) HMMA GEMM (R10-proven) + fused side-work row -------------
__global__ void __launch_bounds__(256)
k_hgemm(const __half* __restrict__ A, const __half* __restrict__ B,
        const float* __restrict__ bias, float* __restrict__ Cf, __half* __restrict__ Ch,
        int Ncols, int mode, const float* __restrict__ gamma,
        int extra, const int* __restrict__ braw,
        const float* __restrict__ wo_src, __half* __restrict__ wo_dst) {
    __shared__ __align__(16) __half sA[2][128 * PAD];
    __shared__ __align__(16) __half sB[2][128 * PAD];

    const int tid = threadIdx.x;

    if (extra && blockIdx.y == gridDim.y - 1) {
        int bx = blockIdx.x;
        if (bx < 8) {
            int* sb = (int*)sA;
            __shared__ int s64;
            if (tid == 0) {
                int acc = 0;
                #pragma unroll
                for (int i = 0; i < 32; i++) acc |= braw[2 * i + 1];
                s64 = (acc == 0);
            }
            __syncthreads();
            for (int i = tid; i < N_TOK; i += 256)
                sb[i] = s64 ? braw[2 * i] : braw[i];
            __syncthreads();
            int i = bx * 256 + tid;
            if (bx == 0) {
                for (int j = tid; j < N_TOK; j += 256) g_bidx[j] = sb[j];
            }
            int b = sb[i];
            int pos = 0;
            for (int j = 0; j < i; j++) pos += (sb[j] == b) ? 1 : 0;
            g_list[b * N_TOK + pos] = i;
            if (bx == 0 && tid < NGRP) {
                int c = 0;
                for (int j = 0; j < N_TOK; j++) c += (sb[j] == tid) ? 1 : 0;
                g_cnt[tid] = c;
            }
        } else {
            for (int i = (bx - 8) * 256 + tid; i < WO4; i += 16 * 256) {
                float4 v = __ldcs(&((const float4*)wo_src)[i]);
                __half hs[4] = { __float2half_rn(v.x), __float2half_rn(v.y),
                                 __float2half_rn(v.z), __float2half_rn(v.w) };
                *(uint2*)&wo_dst[i * 4] = *(uint2*)hs;
            }
        }
        return;
    }

    const int warp = tid >> 5, lane = tid & 31;
    const int wm = warp >> 2, wn = warp & 3;
    const int bM = blockIdx.y * 128, bN = blockIdx.x * 128;

    float acc[4][4][4];
    #pragma unroll
    for (int i = 0; i < 4; i++)
        #pragma unroll
        for (int j = 0; j < 4; j++)
            #pragma unroll
            for (int c = 0; c < 4; c++) acc[i][j][c] = 0.f;

    const int lr = tid >> 2, lc = (tid & 3) * 8;
    const int a_row = lane & 15, a_k = (lane >> 4) * 8;
    const int b_row = (lane & 7) + ((lane >> 4) << 3);
    const int b_k   = ((lane >> 3) & 1) * 8;
    const uint32_t sA_b = smem_u32(sA), sB_b = smem_u32(sB);

    #define LOAD_STAGE(kc, st) do {                                           \
        uint32_t so = (uint32_t)(st) * (128 * PAD * 2);                       \
        size_t ga0 = (size_t)(bM + lr)      * C_DIM + (kc) * 32 + lc;         \
        size_t ga1 = (size_t)(bM + lr + 64) * C_DIM + (kc) * 32 + lc;         \
        size_t gb0 = (size_t)(bN + lr)      * C_DIM + (kc) * 32 + lc;         \
        size_t gb1 = (size_t)(bN + lr + 64) * C_DIM + (kc) * 32 + lc;         \
        cp16(sA_b + so + (lr * PAD + lc) * 2,        A + ga0);                \
        cp16(sA_b + so + ((lr + 64) * PAD + lc) * 2, A + ga1);                \
        cp16(sB_b + so + (lr * PAD + lc) * 2,        B + gb0);                \
        cp16(sB_b + so + ((lr + 64) * PAD + lc) * 2, B + gb1);                \
        asm volatile("cp.async.commit_group;");                               \
    } while (0)

    LOAD_STAGE(0, 0);
    for (int kc = 0; kc < 32; kc++) {
        int cur = kc & 1;
        if (kc < 31) {
            LOAD_STAGE(kc + 1, cur ^ 1);
            asm volatile("cp.async.wait_group 1;");
        } else {
            asm volatile("cp.async.wait_group 0;");
        }
        __syncthreads();
        uint32_t so = (uint32_t)cur * (128 * PAD * 2);
        #pragma unroll
        for (int ks = 0; ks < 32; ks += 16) {
            uint32_t aF[4][4], bF[4][2];
            #pragma unroll
            for (int i = 0; i < 4; i++) {
                uint32_t off = so + (uint32_t)((wm * 64 + i * 16 + a_row) * PAD + ks + a_k) * 2;
                LDSM4(aF[i], sA_b + off);
            }
            #pragma unroll
            for (int jj = 0; jj < 2; jj++) {
                uint32_t off = so + (uint32_t)((wn * 32 + jj * 16 + b_row) * PAD + ks + b_k) * 2;
                uint32_t r[4];
                LDSM4(r, sB_b + off);
                bF[jj * 2 + 0][0] = r[0]; bF[jj * 2 + 0][1] = r[1];
                bF[jj * 2 + 1][0] = r[2]; bF[jj * 2 + 1][1] = r[3];
            }
            #pragma unroll
            for (int i = 0; i < 4; i++)
                #pragma unroll
                for (int j = 0; j < 4; j++)
                    MMA16816(acc[i][j], aF[i], bF[j]);
        }
        __syncthreads();
    }

    const int g4 = lane >> 2, t4 = lane & 3;
    #pragma unroll
    for (int i = 0; i < 4; i++) {
        int r0 = bM + wm * 64 + i * 16 + g4;
        int r1 = r0 + 8;
        float gm0 = 1.f, gm1 = 1.f;
        if (mode == 1) {
            gm0 = (g_cnt[g_bidx[r0]] > 1) ? gamma[0] : 0.0f;
            gm1 = (g_cnt[g_bidx[r1]] > 1) ? gamma[0] : 0.0f;
        }
        #pragma unroll
        for (int j = 0; j < 4; j++) {
            int c = bN + wn * 32 + j * 8 + 2 * t4;
            float b0 = bias[c], b1 = bias[c + 1];
            if (mode == 1) {
                float2 o0 = { (acc[i][j][0] + b0) * gm0, (acc[i][j][1] + b1) * gm0 };
                float2 o1 = { (acc[i][j][2] + b0) * gm1, (acc[i][j][3] + b1) * gm1 };
                *(float2*)&Cf[(size_t)r0 * Ncols + c] = o0;
                *(float2*)&Cf[(size_t)r1 * Ncols + c] = o1;
            } else {
                __half h0[2] = { __float2half_rn(acc[i][j][0] + b0),
                                 __float2half_rn(acc[i][j][1] + b1) };
                __half h1[2] = { __float2half_rn(acc[i][j][2] + b0),
                                 __float2half_rn(acc[i][j][3] + b1) };
                *(uint32_t*)&Ch[(size_t)r0 * Ncols + c] = *(uint32_t*)h0;
                *(uint32_t*)&Ch[(size_t)r1 * Ncols + c] = *(uint32_t*)h1;
            }
        }
    }
}

// ---------------- 5) flash attention: 256 blocks, q-chunk loop ----------------
__global__ void __launch_bounds__(128) k_attn() {
    int bx = blockIdx.x;                 // 256 blocks: h*NGRP + g
    int g  = bx & (NGRP - 1);
    int h  = bx >> 5;
    int m  = g_cnt[g];

    int tid = threadIdx.x, w = tid >> 5, lane = tid & 31;
    __shared__ __align__(16) __half Qs[64 * ATS];
    __shared__ __align__(16) __half Ks[32 * ATS];
    __shared__ __align__(16) __half Vs[32 * ATS];
    const uint32_t qs_b = smem_u32(Qs), ks_b = smem_u32(Ks), vs_b = smem_u32(Vs);

    const int a_row = lane & 15, a_k = (lane >> 4) * 8;
    const int b_row = (lane & 7) + ((lane >> 4) << 3);
    const int b_k   = ((lane >> 3) & 1) * 8;
    const int vrow  = (lane & 7) + ((lane >> 3) & 1) * 8;
    const int vcol  = (lane >> 4) * 8;
    const float SC  = 0.08838834764831845f;

    for (int q0 = 0; q0 < m; q0 += 64) {
        // ---- load Q tile (64 x 128), zero-filled ----
        #pragma unroll
        for (int it = 0; it < 8; it++) {
            int p = tid + it * 128;
            int r = p >> 4, c = p & 15;
            int qi = q0 + r;
            uint4 v = {0, 0, 0, 0};
            if (qi < m) {
                int tok = g_list[g * N_TOK + qi];
                v = *(const uint4*)&g_qkvh[(size_t)tok * 3072 + h * HD + c * 8];
            }
            *(uint4*)&Qs[r * ATS + c * 8] = v;
        }
        __syncthreads();

        uint32_t qf[8][4];
        #pragma unroll
        for (int ks = 0; ks < 8; ks++) {
            uint32_t off = (uint32_t)((w * 16 + a_row) * ATS + ks * 16 + a_k) * 2;
            LDSM4(qf[ks], qs_b + off);
        }

        float o[16][4];
        #pragma unroll
        for (int n = 0; n < 16; n++) { o[n][0] = o[n][1] = o[n][2] = o[n][3] = 0.f; }
        float mx0 = -1e30f, mx1 = -1e30f, l0 = 0.f, l1 = 0.f;

        for (int kbase = 0; kbase < m; kbase += 32) {
            __syncthreads();   // previous tile's (and chunk's) smem reads done
            #pragma unroll
            for (int it = 0; it < 8; it++) {
                int p = tid + it * 128;
                int isV = p >> 9;
                int q = p & 511;
                int r = q >> 4, c = q & 15;
                int kj = kbase + r;
                uint4 v = {0, 0, 0, 0};
                if (kj < m) {
                    int tok = g_list[g * N_TOK + kj];
                    v = *(const uint4*)&g_qkvh[(size_t)tok * 3072 + (1 + isV) * C_DIM + h * HD + c * 8];
                }
                if (isV) *(uint4*)&Vs[r * ATS + c * 8] = v;
                else     *(uint4*)&Ks[r * ATS + c * 8] = v;
            }
            __syncthreads();

            float s[4][4];
            #pragma unroll
            for (int T = 0; T < 4; T++) { s[T][0] = s[T][1] = s[T][2] = s[T][3] = 0.f; }
            #pragma unroll
            for (int ks = 0; ks < 8; ks++) {
                uint32_t r0[4], r1[4];
                LDSM4(r0, ks_b + (uint32_t)((0  + b_row) * ATS + ks * 16 + b_k) * 2);
                LDSM4(r1, ks_b + (uint32_t)((16 + b_row) * ATS + ks * 16 + b_k) * 2);
                uint32_t bA[2] = { r0[0], r0[1] }, bB[2] = { r0[2], r0[3] };
                uint32_t bC[2] = { r1[0], r1[1] }, bD[2] = { r1[2], r1[3] };
                MMA16816(s[0], qf[ks], bA);
                MMA16816(s[1], qf[ks], bB);
                MMA16816(s[2], qf[ks], bC);
                MMA16816(s[3], qf[ks], bD);
            }

            int cbase = kbase + 2 * (lane & 3);
            #pragma unroll
            for (int T = 0; T < 4; T++) {
                int k0 = cbase + T * 8;
                s[T][0] = (k0     < m) ? s[T][0] * SC : -1e30f;
                s[T][1] = (k0 + 1 < m) ? s[T][1] * SC : -1e30f;
                s[T][2] = (k0     < m) ? s[T][2] * SC : -1e30f;
                s[T][3] = (k0 + 1 < m) ? s[T][3] * SC : -1e30f;
            }

            float m0 = s[0][0], m1 = s[0][2];
            #pragma unroll
            for (int T = 0; T < 4; T++) {
                m0 = fmaxf(m0, fmaxf(s[T][0], s[T][1]));
                m1 = fmaxf(m1, fmaxf(s[T][2], s[T][3]));
            }
            m0 = fmaxf(m0, __shfl_xor_sync(0xffffffffu, m0, 1));
            m0 = fmaxf(m0, __shfl_xor_sync(0xffffffffu, m0, 2));
            m1 = fmaxf(m1, __shfl_xor_sync(0xffffffffu, m1, 1));
            m1 = fmaxf(m1, __shfl_xor_sync(0xffffffffu, m1, 2));
            float mn0 = fmaxf(mx0, m0), mn1 = fmaxf(mx1, m1);
            float c0 = __expf(mx0 - mn0), c1 = __expf(mx1 - mn1);

            float p[4][4];
            float s0 = 0.f, s1 = 0.f;
            #pragma unroll
            for (int T = 0; T < 4; T++) {
                p[T][0] = __expf(s[T][0] - mn0);
                p[T][1] = __expf(s[T][1] - mn0);
                p[T][2] = __expf(s[T][2] - mn1);
                p[T][3] = __expf(s[T][3] - mn1);
                s0 += p[T][0] + p[T][1];
                s1 += p[T][2] + p[T][3];
            }
            s0 += __shfl_xor_sync(0xffffffffu, s0, 1);
            s0 += __shfl_xor_sync(0xffffffffu, s0, 2);
            s1 += __shfl_xor_sync(0xffffffffu, s1, 1);
            s1 += __shfl_xor_sync(0xffffffffu, s1, 2);
            l0 = l0 * c0 + s0;
            l1 = l1 * c1 + s1;
            mx0 = mn0; mx1 = mn1;

            #pragma unroll
            for (int n = 0; n < 16; n++) {
                o[n][0] *= c0; o[n][1] *= c0; o[n][2] *= c1; o[n][3] *= c1;
            }

            uint32_t pf[2][4];
            #pragma unroll
            for (int kst = 0; kst < 2; kst++) {
                int T0 = kst * 2;
                __half2 h0 = __floats2half2_rn(p[T0][0],     p[T0][1]);
                __half2 h1 = __floats2half2_rn(p[T0][2],     p[T0][3]);
                __half2 h2 = __floats2half2_rn(p[T0 + 1][0], p[T0 + 1][1]);
                __half2 h3 = __floats2half2_rn(p[T0 + 1][2], p[T0 + 1][3]);
                pf[kst][0] = *(uint32_t*)&h0;
                pf[kst][1] = *(uint32_t*)&h1;
                pf[kst][2] = *(uint32_t*)&h2;
                pf[kst][3] = *(uint32_t*)&h3;
            }

            #pragma unroll
            for (int kst = 0; kst < 2; kst++) {
                #pragma unroll
                for (int dt = 0; dt < 8; dt++) {
                    uint32_t r[4];
                    LDSM4T(r, vs_b + (uint32_t)((kst * 16 + vrow) * ATS + dt * 16 + vcol) * 2);
                    uint32_t bA[2] = { r[0], r[1] }, bB[2] = { r[2], r[3] };
                    MMA16816(o[dt * 2],     pf[kst], bA);
                    MMA16816(o[dt * 2 + 1], pf[kst], bB);
                }
            }
        }

        float inv0 = 1.0f / l0, inv1 = 1.0f / l1;
        int qi0 = q0 + w * 16 + (lane >> 2);
        int qi1 = qi0 + 8;
        int tok0 = (qi0 < m) ? g_list[g * N_TOK + qi0] : -1;
        int tok1 = (qi1 < m) ? g_list[g * N_TOK + qi1] : -1;
        int colb = h * HD + 2 * (lane & 3);
        #pragma unroll
        for (int dt = 0; dt < 16; dt++) {
            if (tok0 >= 0) {
                __half2 hv = __floats2half2_rn(o[dt][0] * inv0, o[dt][1] * inv0);
                *(uint32_t*)&g_a[(size_t)tok0 * C_DIM + colb + dt * 8] = *(uint32_t*)&hv;
            }
            if (tok1 >= 0) {
                __half2 hv = __floats2half2_rn(o[dt][2] * inv1, o[dt][3] * inv1);
                *(uint32_t*)&g_a[(size_t)tok1 * C_DIM + colb + dt * 8] = *(uint32_t*)&hv;
            }
        }
        __syncthreads();   // all warps done with Qs/Ks/Vs before next chunk
    }
}

// ---------------- 6) y = x + coef[n,c] ---------------------------------------
__global__ void k_add(const float* __restrict__ x, float* __restrict__ y) {
    const float4* x4 = (const float4*)x;
    float4* y4 = (float4*)y;
    const int total = N_TOK * C_DIM * (HW / 4);
    int stride = gridDim.x * blockDim.x;
    for (int i = blockIdx.x * blockDim.x + threadIdx.x; i < total; i += stride) {
        float c = g_coef[i >> 4];
        float4 v = x4[i];
        v.x += c; v.y += c; v.z += c; v.w += c;
        y4[i] = v;
    }
}

// ---------------- launch ------------------------------------------------------
extern "C" void kernel_launch(void* const* d_in, const int* in_sizes, int n_in,
                              void* d_out, int out_size) {
    const float* x          = (const float*)d_in[0];
    const int*   braw       = (const int*)  d_in[1];
    const float* ln_w       = (const float*)d_in[2];
    const float* ln_b       = (const float*)d_in[3];
    const float* in_proj_w  = (const float*)d_in[4];
    const float* in_proj_b  = (const float*)d_in[5];
    const float* out_proj_w = (const float*)d_in[6];
    const float* out_proj_b = (const float*)d_in[7];
    const float* gamma      = (const float*)d_in[8];
    float* y = (float*)d_out;

    __half *p_f, *p_wq, *p_wo, *p_a, *p_qkvh;
    float *p_coef;
    cudaGetSymbolAddress((void**)&p_f,    g_f);
    cudaGetSymbolAddress((void**)&p_wq,   g_wq);
    cudaGetSymbolAddress((void**)&p_wo,   g_wo);
    cudaGetSymbolAddress((void**)&p_a,    g_a);
    cudaGetSymbolAddress((void**)&p_qkvh, g_qkvh);
    cudaGetSymbolAddress((void**)&p_coef, g_coef);

    // Single stream; overlap via block-range fusion. slot 4 (ncu) = k_attn.
    k_pre  <<<MEANB + 3072, 256>>>(x, in_proj_w, p_wq);
    k_ln   <<<256, 256>>>(ln_w, ln_b);
    k_hgemm<<<dim3(24, 17), 256>>>(p_f, p_wq, in_proj_b, nullptr, p_qkvh,
                                   3 * C_DIM, 0, nullptr,
                                   1, braw, out_proj_w, p_wo);
    k_attn <<<NHEAD * NGRP, 128>>>();
    k_hgemm<<<dim3(8, 16), 256>>>(p_a, p_wo, out_proj_b, p_coef, nullptr,
                                  C_DIM, 1, gamma,
                                  0, nullptr, nullptr, nullptr);
    k_add  <<<32768, 256>>>(x, y);
}

// round 17
// speedup vs baseline: 1.0811x; 1.0006x over previous
#include <cuda_runtime.h>
#include <cuda_fp16.h>
#include <stdint.h>
#include <math.h>

#define N_TOK 2048
#define C_DIM 1024
#define NHEAD 8
#define HD    128
#define NGRP  32
#define HW    64
#define PAD   40    // GEMM smem stride (halfs)
#define ATS   136   // attention smem stride (halfs)
#define WQ4   (3 * C_DIM * C_DIM / 4)
#define WO4   (C_DIM * C_DIM / 4)
#define MEANB 1184

// ---------------- scratch ----------------------------------------------------
__device__ float g_feat[N_TOK * C_DIM];
__device__ float g_coef[N_TOK * C_DIM];
__device__ int   g_bidx[N_TOK];
__device__ int   g_cnt [NGRP];
__device__ int   g_list[NGRP * N_TOK];
__device__ __half g_f   [N_TOK * C_DIM];
__device__ __half g_qkvh[N_TOK * 3 * C_DIM];
__device__ __half g_wq  [3 * C_DIM * C_DIM];
__device__ __half g_wo  [C_DIM * C_DIM];
__device__ __half g_a   [N_TOK * C_DIM];

__device__ __forceinline__ uint32_t smem_u32(const void* p) {
    uint32_t a;
    asm("{ .reg .u64 t; cvta.to.shared.u64 t, %1; cvt.u32.u64 %0, t; }" : "=r"(a) : "l"(p));
    return a;
}
__device__ __forceinline__ void cp16(uint32_t dst, const void* src) {
    asm volatile("cp.async.cg.shared.global [%0], [%1], 16;" :: "r"(dst), "l"(src));
}
#define MMA16816(d, a, b)                                                       \
    asm volatile("mma.sync.aligned.m16n8k16.row.col.f32.f16.f16.f32 "           \
        "{%0,%1,%2,%3}, {%4,%5,%6,%7}, {%8,%9}, {%0,%1,%2,%3};"                 \
        : "+f"((d)[0]), "+f"((d)[1]), "+f"((d)[2]), "+f"((d)[3])                \
        : "r"((a)[0]), "r"((a)[1]), "r"((a)[2]), "r"((a)[3]),                   \
          "r"((b)[0]), "r"((b)[1]))
#define LDSM4(r, addr)                                                          \
    asm volatile("ldmatrix.sync.aligned.m8n8.x4.shared.b16 {%0,%1,%2,%3}, [%4];"\
        : "=r"((r)[0]), "=r"((r)[1]), "=r"((r)[2]), "=r"((r)[3]) : "r"(addr))
#define LDSM4T(r, addr)                                                         \
    asm volatile("ldmatrix.sync.aligned.m8n8.x4.trans.shared.b16 {%0,%1,%2,%3}, [%4];"\
        : "=r"((r)[0]), "=r"((r)[1]), "=r"((r)[2]), "=r"((r)[3]) : "r"(addr))

// ---------------- 1) k_pre: mean over H*W + wq fp32->fp16 --------------------
__global__ void k_pre(const float* __restrict__ x,
                      const float* __restrict__ wq_src, __half* __restrict__ wq_dst) {
    if (blockIdx.x < MEANB) {
        const float4* x4 = (const float4*)x;
        int gw    = (blockIdx.x * blockDim.x + threadIdx.x) >> 5;
        int lane  = threadIdx.x & 31;
        int nwarp = (MEANB * 256) >> 5;
        const int CHUNKS = N_TOK * C_DIM / 16;
        for (int ch = gw; ch < CHUNKS; ch += nwarp) {
            size_t base = (size_t)ch * 256 + lane;
            float4 v[8];
            #pragma unroll
            for (int j = 0; j < 8; j++) v[j] = __ldcs(&x4[base + 32 * j]);
            float s[8];
            #pragma unroll
            for (int j = 0; j < 8; j++) s[j] = (v[j].x + v[j].y) + (v[j].z + v[j].w);
            #pragma unroll
            for (int j = 0; j < 8; j++) {
                s[j] += __shfl_xor_sync(0xffffffffu, s[j], 8);
                s[j] += __shfl_xor_sync(0xffffffffu, s[j], 4);
                s[j] += __shfl_xor_sync(0xffffffffu, s[j], 2);
                s[j] += __shfl_xor_sync(0xffffffffu, s[j], 1);
            }
            if (lane == 0 || lane == 16) {
                int r0 = ch * 16 + (lane >> 4);
                #pragma unroll
                for (int j = 0; j < 8; j++) g_feat[r0 + 2 * j] = s[j] * (1.0f / 64.0f);
            }
        }
    } else {
        int i = (blockIdx.x - MEANB) * blockDim.x + threadIdx.x;
        if (i < WQ4) {
            float4 v = __ldcs(&((const float4*)wq_src)[i]);
            __half hs[4] = { __float2half_rn(v.x), __float2half_rn(v.y),
                             __float2half_rn(v.z), __float2half_rn(v.w) };
            *(uint2*)&wq_dst[i * 4] = *(uint2*)hs;
        }
    }
}

// ---------------- 3) LayerNorm: warp per token --------------------------------
__global__ void __launch_bounds__(256) k_ln(const float* __restrict__ w,
                                            const float* __restrict__ b) {
    int warp = threadIdx.x >> 5, lane = threadIdx.x & 31;
    int tok = blockIdx.x * 8 + warp;
    const float4* f4 = (const float4*)g_feat + (size_t)tok * 256;
    float4 v[8];
    #pragma unroll
    for (int i = 0; i < 8; i++) v[i] = f4[lane + i * 32];
    float s = 0.f, sq = 0.f;
    #pragma unroll
    for (int i = 0; i < 8; i++) {
        s  += (v[i].x + v[i].y) + (v[i].z + v[i].w);
        sq += (v[i].x * v[i].x + v[i].y * v[i].y)
            + (v[i].z * v[i].z + v[i].w * v[i].w);
    }
    #pragma unroll
    for (int off = 16; off; off >>= 1) {
        s  += __shfl_xor_sync(0xffffffffu, s,  off);
        sq += __shfl_xor_sync(0xffffffffu, sq, off);
    }
    float mu   = s * (1.0f / C_DIM);
    float var  = sq * (1.0f / C_DIM) - mu * mu;
    float rstd = rsqrtf(var + 1e-5f);
    #pragma unroll
    for (int i = 0; i < 8; i++) {
        int c4 = lane + i * 32;
        float4 wv = ((const float4*)w)[c4], bv = ((const float4*)b)[c4];
        __half hs[4];
        hs[0] = __float2half_rn((v[i].x - mu) * rstd * wv.x + bv.x);
        hs[1] = __float2half_rn((v[i].y - mu) * rstd * wv.y + bv.y);
        hs[2] = __float2half_rn((v[i].z - mu) * rstd * wv.z + bv.z);
        hs[3] = __float2half_rn((v[i].w - mu) * rstd * wv.w + bv.w);
        *(uint2*)&g_f[(size_t)tok * C_DIM + c4 * 4] = *(uint2*)hs;
    }
}

// ---------------- 4) HMMA GEMM (R10-proven) + fused side-work row -------------
__global__ void __launch_bounds__(256)
k_hgemm(const __half* __restrict__ A, const __half* __restrict__ B,
        const float* __restrict__ bias, float* __restrict__ Cf, __half* __restrict__ Ch,
        int Ncols, int mode, const float* __restrict__ gamma,
        int extra, const int* __restrict__ braw,
        const float* __restrict__ wo_src, __half* __restrict__ wo_dst) {
    __shared__ __align__(16) __half sA[2][128 * PAD];
    __shared__ __align__(16) __half sB[2][128 * PAD];

    const int tid = threadIdx.x;

    if (extra && blockIdx.y == gridDim.y - 1) {
        int bx = blockIdx.x;
        if (bx < 8) {
            int* sb = (int*)sA;
            __shared__ int s64;
            if (tid == 0) {
                int acc = 0;
                #pragma unroll
                for (int i = 0; i < 32; i++) acc |= braw[2 * i + 1];
                s64 = (acc == 0);
            }
            __syncthreads();
            for (int i = tid; i < N_TOK; i += 256)
                sb[i] = s64 ? braw[2 * i] : braw[i];
            __syncthreads();
            int i = bx * 256 + tid;
            if (bx == 0) {
                for (int j = tid; j < N_TOK; j += 256) g_bidx[j] = sb[j];
            }
            int b = sb[i];
            int pos = 0;
            for (int j = 0; j < i; j++) pos += (sb[j] == b) ? 1 : 0;
            g_list[b * N_TOK + pos] = i;
            if (bx == 0 && tid < NGRP) {
                int c = 0;
                for (int j = 0; j < N_TOK; j++) c += (sb[j] == tid) ? 1 : 0;
                g_cnt[tid] = c;
            }
        } else {
            for (int i = (bx - 8) * 256 + tid; i < WO4; i += 16 * 256) {
                float4 v = __ldcs(&((const float4*)wo_src)[i]);
                __half hs[4] = { __float2half_rn(v.x), __float2half_rn(v.y),
                                 __float2half_rn(v.z), __float2half_rn(v.w) };
                *(uint2*)&wo_dst[i * 4] = *(uint2*)hs;
            }
        }
        return;
    }

    const int warp = tid >> 5, lane = tid & 31;
    const int wm = warp >> 2, wn = warp & 3;
    const int bM = blockIdx.y * 128, bN = blockIdx.x * 128;

    float acc[4][4][4];
    #pragma unroll
    for (int i = 0; i < 4; i++)
        #pragma unroll
        for (int j = 0; j < 4; j++)
            #pragma unroll
            for (int c = 0; c < 4; c++) acc[i][j][c] = 0.f;

    const int lr = tid >> 2, lc = (tid & 3) * 8;
    const int a_row = lane & 15, a_k = (lane >> 4) * 8;
    const int b_row = (lane & 7) + ((lane >> 4) << 3);
    const int b_k   = ((lane >> 3) & 1) * 8;
    const uint32_t sA_b = smem_u32(sA), sB_b = smem_u32(sB);

    #define LOAD_STAGE(kc, st) do {                                           \
        uint32_t so = (uint32_t)(st) * (128 * PAD * 2);                       \
        size_t ga0 = (size_t)(bM + lr)      * C_DIM + (kc) * 32 + lc;         \
        size_t ga1 = (size_t)(bM + lr + 64) * C_DIM + (kc) * 32 + lc;         \
        size_t gb0 = (size_t)(bN + lr)      * C_DIM + (kc) * 32 + lc;         \
        size_t gb1 = (size_t)(bN + lr + 64) * C_DIM + (kc) * 32 + lc;         \
        cp16(sA_b + so + (lr * PAD + lc) * 2,        A + ga0);                \
        cp16(sA_b + so + ((lr + 64) * PAD + lc) * 2, A + ga1);                \
        cp16(sB_b + so + (lr * PAD + lc) * 2,        B + gb0);                \
        cp16(sB_b + so + ((lr + 64) * PAD + lc) * 2, B + gb1);                \
        asm volatile("cp.async.commit_group;");                               \
    } while (0)

    LOAD_STAGE(0, 0);
    for (int kc = 0; kc < 32; kc++) {
        int cur = kc & 1;
        if (kc < 31) {
            LOAD_STAGE(kc + 1, cur ^ 1);
            asm volatile("cp.async.wait_group 1;");
        } else {
            asm volatile("cp.async.wait_group 0;");
        }
        __syncthreads();
        uint32_t so = (uint32_t)cur * (128 * PAD * 2);
        #pragma unroll
        for (int ks = 0; ks < 32; ks += 16) {
            uint32_t aF[4][4], bF[4][2];
            #pragma unroll
            for (int i = 0; i < 4; i++) {
                uint32_t off = so + (uint32_t)((wm * 64 + i * 16 + a_row) * PAD + ks + a_k) * 2;
                LDSM4(aF[i], sA_b + off);
            }
            #pragma unroll
            for (int jj = 0; jj < 2; jj++) {
                uint32_t off = so + (uint32_t)((wn * 32 + jj * 16 + b_row) * PAD + ks + b_k) * 2;
                uint32_t r[4];
                LDSM4(r, sB_b + off);
                bF[jj * 2 + 0][0] = r[0]; bF[jj * 2 + 0][1] = r[1];
                bF[jj * 2 + 1][0] = r[2]; bF[jj * 2 + 1][1] = r[3];
            }
            #pragma unroll
            for (int i = 0; i < 4; i++)
                #pragma unroll
                for (int j = 0; j < 4; j++)
                    MMA16816(acc[i][j], aF[i], bF[j]);
        }
        __syncthreads();
    }

    const int g4 = lane >> 2, t4 = lane & 3;
    #pragma unroll
    for (int i = 0; i < 4; i++) {
        int r0 = bM + wm * 64 + i * 16 + g4;
        int r1 = r0 + 8;
        float gm0 = 1.f, gm1 = 1.f;
        if (mode == 1) {
            gm0 = (g_cnt[g_bidx[r0]] > 1) ? gamma[0] : 0.0f;
            gm1 = (g_cnt[g_bidx[r1]] > 1) ? gamma[0] : 0.0f;
        }
        #pragma unroll
        for (int j = 0; j < 4; j++) {
            int c = bN + wn * 32 + j * 8 + 2 * t4;
            float b0 = bias[c], b1 = bias[c + 1];
            if (mode == 1) {
                float2 o0 = { (acc[i][j][0] + b0) * gm0, (acc[i][j][1] + b1) * gm0 };
                float2 o1 = { (acc[i][j][2] + b0) * gm1, (acc[i][j][3] + b1) * gm1 };
                *(float2*)&Cf[(size_t)r0 * Ncols + c] = o0;
                *(float2*)&Cf[(size_t)r1 * Ncols + c] = o1;
            } else {
                __half h0[2] = { __float2half_rn(acc[i][j][0] + b0),
                                 __float2half_rn(acc[i][j][1] + b1) };
                __half h1[2] = { __float2half_rn(acc[i][j][2] + b0),
                                 __float2half_rn(acc[i][j][3] + b1) };
                *(uint32_t*)&Ch[(size_t)r0 * Ncols + c] = *(uint32_t*)h0;
                *(uint32_t*)&Ch[(size_t)r1 * Ncols + c] = *(uint32_t*)h1;
            }
        }
    }
}

// ---------------- 5) flash attention: 256 blocks, q-chunk loop ----------------
__global__ void __launch_bounds__(128) k_attn() {
    int bx = blockIdx.x;                 // 256 blocks: h*NGRP + g
    int g  = bx & (NGRP - 1);
    int h  = bx >> 5;
    int m  = g_cnt[g];

    int tid = threadIdx.x, w = tid >> 5, lane = tid & 31;
    __shared__ __align__(16) __half Qs[64 * ATS];
    __shared__ __align__(16) __half Ks[32 * ATS];
    __shared__ __align__(16) __half Vs[32 * ATS];
    const uint32_t qs_b = smem_u32(Qs), ks_b = smem_u32(Ks), vs_b = smem_u32(Vs);

    const int a_row = lane & 15, a_k = (lane >> 4) * 8;
    const int b_row = (lane & 7) + ((lane >> 4) << 3);
    const int b_k   = ((lane >> 3) & 1) * 8;
    const int vrow  = (lane & 7) + ((lane >> 3) & 1) * 8;
    const int vcol  = (lane >> 4) * 8;
    const float SC  = 0.08838834764831845f;

    for (int q0 = 0; q0 < m; q0 += 64) {
        // ---- load Q tile (64 x 128), zero-filled ----
        #pragma unroll
        for (int it = 0; it < 8; it++) {
            int p = tid + it * 128;
            int r = p >> 4, c = p & 15;
            int qi = q0 + r;
            uint4 v = {0, 0, 0, 0};
            if (qi < m) {
                int tok = g_list[g * N_TOK + qi];
                v = *(const uint4*)&g_qkvh[(size_t)tok * 3072 + h * HD + c * 8];
            }
            *(uint4*)&Qs[r * ATS + c * 8] = v;
        }
        __syncthreads();

        uint32_t qf[8][4];
        #pragma unroll
        for (int ks = 0; ks < 8; ks++) {
            uint32_t off = (uint32_t)((w * 16 + a_row) * ATS + ks * 16 + a_k) * 2;
            LDSM4(qf[ks], qs_b + off);
        }

        float o[16][4];
        #pragma unroll
        for (int n = 0; n < 16; n++) { o[n][0] = o[n][1] = o[n][2] = o[n][3] = 0.f; }
        float mx0 = -1e30f, mx1 = -1e30f, l0 = 0.f, l1 = 0.f;

        for (int kbase = 0; kbase < m; kbase += 32) {
            __syncthreads();   // previous tile's (and chunk's) smem reads done
            #pragma unroll
            for (int it = 0; it < 8; it++) {
                int p = tid + it * 128;
                int isV = p >> 9;
                int q = p & 511;
                int r = q >> 4, c = q & 15;
                int kj = kbase + r;
                uint4 v = {0, 0, 0, 0};
                if (kj < m) {
                    int tok = g_list[g * N_TOK + kj];
                    v = *(const uint4*)&g_qkvh[(size_t)tok * 3072 + (1 + isV) * C_DIM + h * HD + c * 8];
                }
                if (isV) *(uint4*)&Vs[r * ATS + c * 8] = v;
                else     *(uint4*)&Ks[r * ATS + c * 8] = v;
            }
            __syncthreads();

            float s[4][4];
            #pragma unroll
            for (int T = 0; T < 4; T++) { s[T][0] = s[T][1] = s[T][2] = s[T][3] = 0.f; }
            #pragma unroll
            for (int ks = 0; ks < 8; ks++) {
                uint32_t r0[4], r1[4];
                LDSM4(r0, ks_b + (uint32_t)((0  + b_row) * ATS + ks * 16 + b_k) * 2);
                LDSM4(r1, ks_b + (uint32_t)((16 + b_row) * ATS + ks * 16 + b_k) * 2);
                uint32_t bA[2] = { r0[0], r0[1] }, bB[2] = { r0[2], r0[3] };
                uint32_t bC[2] = { r1[0], r1[1] }, bD[2] = { r1[2], r1[3] };
                MMA16816(s[0], qf[ks], bA);
                MMA16816(s[1], qf[ks], bB);
                MMA16816(s[2], qf[ks], bC);
                MMA16816(s[3], qf[ks], bD);
            }

            int cbase = kbase + 2 * (lane & 3);
            #pragma unroll
            for (int T = 0; T < 4; T++) {
                int k0 = cbase + T * 8;
                s[T][0] = (k0     < m) ? s[T][0] * SC : -1e30f;
                s[T][1] = (k0 + 1 < m) ? s[T][1] * SC : -1e30f;
                s[T][2] = (k0     < m) ? s[T][2] * SC : -1e30f;
                s[T][3] = (k0 + 1 < m) ? s[T][3] * SC : -1e30f;
            }

            float m0 = s[0][0], m1 = s[0][2];
            #pragma unroll
            for (int T = 0; T < 4; T++) {
                m0 = fmaxf(m0, fmaxf(s[T][0], s[T][1]));
                m1 = fmaxf(m1, fmaxf(s[T][2], s[T][3]));
            }
            m0 = fmaxf(m0, __shfl_xor_sync(0xffffffffu, m0, 1));
            m0 = fmaxf(m0, __shfl_xor_sync(0xffffffffu, m0, 2));
            m1 = fmaxf(m1, __shfl_xor_sync(0xffffffffu, m1, 1));
            m1 = fmaxf(m1, __shfl_xor_sync(0xffffffffu, m1, 2));
            float mn0 = fmaxf(mx0, m0), mn1 = fmaxf(mx1, m1);
            float c0 = __expf(mx0 - mn0), c1 = __expf(mx1 - mn1);

            float p[4][4];
            float s0 = 0.f, s1 = 0.f;
            #pragma unroll
            for (int T = 0; T < 4; T++) {
                p[T][0] = __expf(s[T][0] - mn0);
                p[T][1] = __expf(s[T][1] - mn0);
                p[T][2] = __expf(s[T][2] - mn1);
                p[T][3] = __expf(s[T][3] - mn1);
                s0 += p[T][0] + p[T][1];
                s1 += p[T][2] + p[T][3];
            }
            s0 += __shfl_xor_sync(0xffffffffu, s0, 1);
            s0 += __shfl_xor_sync(0xffffffffu, s0, 2);
            s1 += __shfl_xor_sync(0xffffffffu, s1, 1);
            s1 += __shfl_xor_sync(0xffffffffu, s1, 2);
            l0 = l0 * c0 + s0;
            l1 = l1 * c1 + s1;
            mx0 = mn0; mx1 = mn1;

            #pragma unroll
            for (int n = 0; n < 16; n++) {
                o[n][0] *= c0; o[n][1] *= c0; o[n][2] *= c1; o[n][3] *= c1;
            }

            uint32_t pf[2][4];
            #pragma unroll
            for (int kst = 0; kst < 2; kst++) {
                int T0 = kst * 2;
                __half2 h0 = __floats2half2_rn(p[T0][0],     p[T0][1]);
                __half2 h1 = __floats2half2_rn(p[T0][2],     p[T0][3]);
                __half2 h2 = __floats2half2_rn(p[T0 + 1][0], p[T0 + 1][1]);
                __half2 h3 = __floats2half2_rn(p[T0 + 1][2], p[T0 + 1][3]);
                pf[kst][0] = *(uint32_t*)&h0;
                pf[kst][1] = *(uint32_t*)&h1;
                pf[kst][2] = *(uint32_t*)&h2;
                pf[kst][3] = *(uint32_t*)&h3;
            }

            #pragma unroll
            for (int kst = 0; kst < 2; kst++) {
                #pragma unroll
                for (int dt = 0; dt < 8; dt++) {
                    uint32_t r[4];
                    LDSM4T(r, vs_b + (uint32_t)((kst * 16 + vrow) * ATS + dt * 16 + vcol) * 2);
                    uint32_t bA[2] = { r[0], r[1] }, bB[2] = { r[2], r[3] };
                    MMA16816(o[dt * 2],     pf[kst], bA);
                    MMA16816(o[dt * 2 + 1], pf[kst], bB);
                }
            }
        }

        float inv0 = 1.0f / l0, inv1 = 1.0f / l1;
        int qi0 = q0 + w * 16 + (lane >> 2);
        int qi1 = qi0 + 8;
        int tok0 = (qi0 < m) ? g_list[g * N_TOK + qi0] : -1;
        int tok1 = (qi1 < m) ? g_list[g * N_TOK + qi1] : -1;
        int colb = h * HD + 2 * (lane & 3);
        #pragma unroll
        for (int dt = 0; dt < 16; dt++) {
            if (tok0 >= 0) {
                __half2 hv = __floats2half2_rn(o[dt][0] * inv0, o[dt][1] * inv0);
                *(uint32_t*)&g_a[(size_t)tok0 * C_DIM + colb + dt * 8] = *(uint32_t*)&hv;
            }
            if (tok1 >= 0) {
                __half2 hv = __floats2half2_rn(o[dt][2] * inv1, o[dt][3] * inv1);
                *(uint32_t*)&g_a[(size_t)tok1 * C_DIM + colb + dt * 8] = *(uint32_t*)&hv;
            }
        }
        __syncthreads();   // all warps done with Qs/Ks/Vs before next chunk
    }
}

// ---------------- 6) y = x + coef[n,c] ---------------------------------------
__global__ void k_add(const float* __restrict__ x, float* __restrict__ y) {
    const float4* x4 = (const float4*)x;
    float4* y4 = (float4*)y;
    const int total = N_TOK * C_DIM * (HW / 4);
    int stride = gridDim.x * blockDim.x;
    for (int i = blockIdx.x * blockDim.x + threadIdx.x; i < total; i += stride) {
        float c = g_coef[i >> 4];
        float4 v = x4[i];
        v.x += c; v.y += c; v.z += c; v.w += c;
        y4[i] = v;
    }
}

// ---------------- launch ------------------------------------------------------
extern "C" void kernel_launch(void* const* d_in, const int* in_sizes, int n_in,
                              void* d_out, int out_size) {
    const float* x          = (const float*)d_in[0];
    const int*   braw       = (const int*)  d_in[1];
    const float* ln_w       = (const float*)d_in[2];
    const float* ln_b       = (const float*)d_in[3];
    const float* in_proj_w  = (const float*)d_in[4];
    const float* in_proj_b  = (const float*)d_in[5];
    const float* out_proj_w = (const float*)d_in[6];
    const float* out_proj_b = (const float*)d_in[7];
    const float* gamma      = (const float*)d_in[8];
    float* y = (float*)d_out;

    __half *p_f, *p_wq, *p_wo, *p_a, *p_qkvh;
    float *p_coef;
    cudaGetSymbolAddress((void**)&p_f,    g_f);
    cudaGetSymbolAddress((void**)&p_wq,   g_wq);
    cudaGetSymbolAddress((void**)&p_wo,   g_wo);
    cudaGetSymbolAddress((void**)&p_a,    g_a);
    cudaGetSymbolAddress((void**)&p_qkvh, g_qkvh);
    cudaGetSymbolAddress((void**)&p_coef, g_coef);

    // Single stream; overlap via block-range fusion. slot 4 (ncu) = k_attn.
    k_pre  <<<MEANB + 3072, 256>>>(x, in_proj_w, p_wq);
    k_ln   <<<256, 256>>>(ln_w, ln_b);
    k_hgemm<<<dim3(24, 17), 256>>>(p_f, p_wq, in_proj_b, nullptr, p_qkvh,
                                   3 * C_DIM, 0, nullptr,
                                   1, braw, out_proj_w, p_wo);
    k_attn <<<NHEAD * NGRP, 128>>>();
    k_hgemm<<<dim3(8, 16), 256>>>(p_a, p_wo, out_proj_b, p_coef, nullptr,
                                  C_DIM, 1, gamma,
                                  0, nullptr, nullptr, nullptr);
    k_add  <<<32768, 256>>>(x, y);
}